// round 3
// baseline (speedup 1.0000x reference)
#include <cuda_runtime.h>
#include <cuda_bf16.h>
#include <cstdint>

#define BSZ   64
#define TT    512
#define DD    512
#define HID   1024
#define G4    4096                 // 4*HID
#define MROWS (BSZ*TT)             // 32768
#define NBLK  128                  // persistent blocks (1 per SM)
#define RT    128                  // threads in recurrent kernel

// ---------------- device scratch (no runtime allocation allowed) -------------
__device__ float    g_Z[(size_t)MROWS * G4];        // gate preactivations (512 MB)
__device__ float    g_H0[(size_t)MROWS * HID];      // layer-0 output seq  (128 MB)
__device__ float    g_Hping[2 * HID * BSZ];         // transposed h ping-pong
__device__ unsigned g_cnt = 0;
__device__ unsigned g_gen = 0;

// =============================================================================
// SGEMM: C[m, n] = sum_k A[m,k]*W[n,k] + bias[n]   (M=32768, N=4096 fixed)
// =============================================================================
__global__ __launch_bounds__(256, 2)
void sgemm_bias(const float* __restrict__ A, int lda,
                const float* __restrict__ Wm, int ldb,
                const float* __restrict__ bias,
                float* __restrict__ C, int K)
{
    __shared__ float As[16][132];
    __shared__ float Bs[16][132];
    const int tid = threadIdx.x;
    const int tx = tid & 15, ty = tid >> 4;
    const int m0 = blockIdx.y * 128;
    const int n0 = blockIdx.x * 128;

    float acc[8][8];
#pragma unroll
    for (int i = 0; i < 8; i++)
#pragma unroll
        for (int j = 0; j < 8; j++) acc[i][j] = 0.f;

    for (int kt = 0; kt < K; kt += 16) {
#pragma unroll
        for (int i = 0; i < 2; i++) {
            int idx = tid + 256 * i;          // 0..511
            int r   = idx >> 2;               // 0..127
            int kq  = (idx & 3) << 2;         // 0,4,8,12
            float4 av = *(const float4*)(A  + (size_t)(m0 + r) * lda + kt + kq);
            As[kq + 0][r] = av.x; As[kq + 1][r] = av.y;
            As[kq + 2][r] = av.z; As[kq + 3][r] = av.w;
            float4 bv = *(const float4*)(Wm + (size_t)(n0 + r) * ldb + kt + kq);
            Bs[kq + 0][r] = bv.x; Bs[kq + 1][r] = bv.y;
            Bs[kq + 2][r] = bv.z; Bs[kq + 3][r] = bv.w;
        }
        __syncthreads();
#pragma unroll
        for (int k = 0; k < 16; k++) {
            float a[8], b[8];
            *(float4*)&a[0] = *(const float4*)&As[k][ty * 8];
            *(float4*)&a[4] = *(const float4*)&As[k][ty * 8 + 4];
            *(float4*)&b[0] = *(const float4*)&Bs[k][tx * 8];
            *(float4*)&b[4] = *(const float4*)&Bs[k][tx * 8 + 4];
#pragma unroll
            for (int i = 0; i < 8; i++)
#pragma unroll
                for (int j = 0; j < 8; j++)
                    acc[i][j] += a[i] * b[j];
        }
        __syncthreads();
    }

    float bi[8];
#pragma unroll
    for (int j = 0; j < 8; j++) bi[j] = bias[n0 + tx * 8 + j];
#pragma unroll
    for (int i = 0; i < 8; i++) {
        size_t row = (size_t)(m0 + ty * 8 + i);
        float4 o0, o1;
        o0.x = acc[i][0] + bi[0]; o0.y = acc[i][1] + bi[1];
        o0.z = acc[i][2] + bi[2]; o0.w = acc[i][3] + bi[3];
        o1.x = acc[i][4] + bi[4]; o1.y = acc[i][5] + bi[5];
        o1.z = acc[i][6] + bi[6]; o1.w = acc[i][7] + bi[7];
        *(float4*)(C + row * G4 + n0 + tx * 8)     = o0;
        *(float4*)(C + row * G4 + n0 + tx * 8 + 4) = o1;
    }
}

// =============================================================================
// Persistent recurrent kernel
// =============================================================================
__device__ __forceinline__ void gridbarrier()
{
    __syncthreads();
    if (threadIdx.x == 0) {
        unsigned gen = *((volatile unsigned*)&g_gen);
        __threadfence();
        if (atomicAdd(&g_cnt, 1u) == NBLK - 1) {
            atomicExch(&g_cnt, 0u);
            __threadfence();
            atomicAdd(&g_gen, 1u);
        } else {
            while (*((volatile unsigned*)&g_gen) == gen) { }
        }
    }
    __syncthreads();
}

__device__ __forceinline__ float fsig(float x)
{
    return __fdividef(1.f, 1.f + __expf(-x));
}
__device__ __forceinline__ float ftanh(float x)
{
    return 2.f * __fdividef(1.f, 1.f + __expf(-2.f * x)) - 1.f;
}

// smem layout (floats):
//   Ws  [1024][36]  transposed weight cache (rows: gate*8+j)
//   hs  [128][68]   h chunk, k-major
//   gs  [64][36]    per-step gate sums
//   cc  [64][8]     cell state (persists across steps)
#define WS_OFF 0
#define HS_OFF (WS_OFF + 1024*36)
#define GS_OFF (HS_OFF + 128*68)
#define CC_OFF (GS_OFF + 64*36)
#define SMEM_FLOATS (CC_OFF + 64*8)

__global__ __launch_bounds__(RT, 1)
void lstm_recur(const float* __restrict__ W, int ldw, int hoff,
                const float* __restrict__ Z,
                float* __restrict__ outSeq)
{
    extern __shared__ float smem[];
    float* Ws = smem + WS_OFF;
    float* hs = smem + HS_OFF;
    float* gs = smem + GS_OFF;
    float* cc = smem + CC_OFF;

    const int tid = threadIdx.x;
    const int blk = blockIdx.x;          // 0..127, owns hidden units blk*8..blk*8+7
    const int rg  = tid & 7;             // row group (4 rows each)
    const int sg  = tid >> 3;            // batch group (4 batches each), 0..15

    // ---- load weight tile transposed: Ws[k][gate*8+j] = W[gate*1024+blk*8+j][hoff+k]
    for (int r = 0; r < 32; r++) {
        int gate = r >> 3, j = r & 7;
        const float* src = W + (size_t)(gate * HID + blk * 8 + j) * ldw + hoff;
        for (int k = tid * 4; k < HID; k += RT * 4) {
            float4 v = *(const float4*)(src + k);
            Ws[(k + 0) * 36 + r] = v.x; Ws[(k + 1) * 36 + r] = v.y;
            Ws[(k + 2) * 36 + r] = v.z; Ws[(k + 3) * 36 + r] = v.w;
        }
    }
    // ---- zero cell state
    for (int i = tid; i < 64 * 8; i += RT) cc[i] = 0.f;
    // ---- cooperatively zero ping buffer 0 (h(-1) = 0)
    for (int i = blk * 512 + tid; i < blk * 512 + 512; i += RT) g_Hping[i] = 0.f;
    __threadfence();
    gridbarrier();

    for (int t = 0; t < TT; t++) {
        const float* hin = g_Hping + (t & 1) * (HID * BSZ);
        float acc[4][4];
#pragma unroll
        for (int i = 0; i < 4; i++)
#pragma unroll
            for (int j = 0; j < 4; j++) acc[i][j] = 0.f;

        for (int kc = 0; kc < HID; kc += 128) {
            __syncthreads();               // previous hs consumers done
            // stage h chunk [128 k][64 s] -> hs
            for (int f = tid; f < 2048; f += RT) {        // 2048 float4s
                int k  = f >> 4;
                int s4 = (f & 15) << 2;
                *(float4*)(hs + k * 68 + s4) =
                    *(const float4*)(hin + (size_t)(kc + k) * 64 + s4);
            }
            __syncthreads();
#pragma unroll 8
            for (int k = 0; k < 128; k++) {
                float4 h4 = *(const float4*)(hs + k * 68 + sg * 4);
                float4 w4 = *(const float4*)(Ws + (size_t)(kc + k) * 36 + rg * 4);
                acc[0][0] += h4.x * w4.x; acc[0][1] += h4.x * w4.y;
                acc[0][2] += h4.x * w4.z; acc[0][3] += h4.x * w4.w;
                acc[1][0] += h4.y * w4.x; acc[1][1] += h4.y * w4.y;
                acc[1][2] += h4.y * w4.z; acc[1][3] += h4.y * w4.w;
                acc[2][0] += h4.z * w4.x; acc[2][1] += h4.z * w4.y;
                acc[2][2] += h4.z * w4.z; acc[2][3] += h4.z * w4.w;
                acc[3][0] += h4.w * w4.x; acc[3][1] += h4.w * w4.y;
                acc[3][2] += h4.w * w4.z; acc[3][3] += h4.w * w4.w;
            }
        }
        // ---- dump partial sums
        __syncthreads();
#pragma unroll
        for (int si = 0; si < 4; si++)
#pragma unroll
            for (int ri = 0; ri < 4; ri++)
                gs[(sg * 4 + si) * 36 + rg * 4 + ri] = acc[si][ri];
        __syncthreads();

        // ---- gate math: 512 cells (64 batches x 8 units), 4 per thread
        float* hout = g_Hping + ((t + 1) & 1) * (HID * BSZ);
#pragma unroll
        for (int it = 0; it < 4; it++) {
            int cid = tid + RT * it;          // 0..511
            int s = cid >> 3, j = cid & 7;
            size_t row = (size_t)s * TT + t;
            const float* zp = Z + row * G4 + blk * 8 + j;
            float zi = zp[0]        + gs[s * 36 +  0 + j];
            float zf = zp[HID]      + gs[s * 36 +  8 + j];
            float zo = zp[2 * HID]  + gs[s * 36 + 16 + j];
            float zg = zp[3 * HID]  + gs[s * 36 + 24 + j];
            float c  = cc[s * 8 + j];
            float cn = fsig(zf) * c + fsig(zi) * ftanh(zg);
            float hn = fsig(zo) * ftanh(cn);
            cc[s * 8 + j] = cn;
            int u = blk * 8 + j;
            outSeq[row * HID + u] = hn;       // sequence output (layer input / final)
            hout[(size_t)u * 64 + s] = hn;    // transposed for next step
        }
        __threadfence();
        gridbarrier();
    }
}

// =============================================================================
extern "C" void kernel_launch(void* const* d_in, const int* in_sizes, int n_in,
                              void* d_out, int out_size)
{
    const float* x  = (const float*)d_in[0];
    const float* W0 = (const float*)d_in[1];
    const float* b0 = (const float*)d_in[2];
    const float* W1 = (const float*)d_in[3];
    const float* b1 = (const float*)d_in[4];
    float* out = (float*)d_out;

    float *pZ = nullptr, *pH0 = nullptr;
    cudaGetSymbolAddress((void**)&pZ,  g_Z);
    cudaGetSymbolAddress((void**)&pH0, g_H0);

    cudaFuncSetAttribute(lstm_recur,
                         cudaFuncAttributeMaxDynamicSharedMemorySize,
                         SMEM_FLOATS * sizeof(float));

    dim3 gg(G4 / 128, MROWS / 128);

    // layer 0
    sgemm_bias<<<gg, 256>>>(x, DD, W0, DD + HID, b0, pZ, DD);
    lstm_recur<<<NBLK, RT, SMEM_FLOATS * sizeof(float)>>>(W0, DD + HID, DD, pZ, pH0);
    // layer 1
    sgemm_bias<<<gg, 256>>>(pH0, HID, W1, HID + HID, b1, pZ, HID);
    lstm_recur<<<NBLK, RT, SMEM_FLOATS * sizeof(float)>>>(W1, HID + HID, HID, pZ, out);
}

// round 5
// speedup vs baseline: 1.1142x; 1.1142x over previous
#include <cuda_runtime.h>
#include <cuda_bf16.h>
#include <cstdint>

#define BSZ   64
#define TT    512
#define DD    512
#define HID   1024
#define G4    4096
#define MROWS (BSZ*TT)             // 32768
#define NBLK  128
#define RT    128
#define MT    (MROWS/128)          // 256 M tiles
#define NT    (G4/128)             // 32  N tiles

// ---------------- device scratch -------------------------------------------
__device__ __align__(16) float    g_Z[(size_t)MROWS * G4];      // 512 MB
__device__ __align__(16) float    g_H0[(size_t)MROWS * HID];    // 128 MB
__device__ __align__(16) float    g_Hping[2 * HID * BSZ];
__device__ unsigned g_cnt = 0;
__device__ unsigned g_gen = 0;
__device__ __align__(16) __nv_bfloat16 g_Apack[(size_t)MROWS * 3 * HID]; // 201 MB
__device__ __align__(16) __nv_bfloat16 g_Bpack[(size_t)G4 * 3 * HID];    // 25 MB

// ---------------- PTX helpers (sm_80-era, family-portable) ------------------
__device__ __forceinline__ uint32_t smem_u32(const void* p)
{
    uint32_t a;
    asm("{ .reg .u64 t; cvta.to.shared.u64 t, %1; cvt.u32.u64 %0, t; }"
        : "=r"(a) : "l"(p));
    return a;
}
__device__ __forceinline__ void cpasync16(uint32_t dst, const void* src)
{
    asm volatile("cp.async.cg.shared.global [%0], [%1], 16;"
                 :: "r"(dst), "l"(src));
}
#define CP_COMMIT() asm volatile("cp.async.commit_group;")
#define CP_WAIT1()  asm volatile("cp.async.wait_group 1;")

__device__ __forceinline__ void ldsm4(uint32_t* r, uint32_t addr)
{
    asm volatile("ldmatrix.sync.aligned.m8n8.x4.shared.b16 {%0,%1,%2,%3}, [%4];"
                 : "=r"(r[0]), "=r"(r[1]), "=r"(r[2]), "=r"(r[3]) : "r"(addr));
}
__device__ __forceinline__ void mma_bf16(float* c, const uint32_t* a,
                                         const uint32_t* b)
{
    asm volatile(
        "mma.sync.aligned.m16n8k16.row.col.f32.bf16.bf16.f32 "
        "{%0,%1,%2,%3}, {%4,%5,%6,%7}, {%8,%9}, {%0,%1,%2,%3};"
        : "+f"(c[0]), "+f"(c[1]), "+f"(c[2]), "+f"(c[3])
        : "r"(a[0]), "r"(a[1]), "r"(a[2]), "r"(a[3]), "r"(b[0]), "r"(b[1]));
}

// =============================================================================
// pack3: fp32 -> bf16x3 row-major panels.
// dst[r][sec*K+col]; A (mode 0): [hi, lo, hi]; B (mode 1): [hi, hi, lo]
// =============================================================================
__global__ void pack3(const float* __restrict__ src, int lds, int cslog2,
                      long nrows, __nv_bfloat16* __restrict__ dst, int mode)
{
    const int K = 8 << cslog2;
    const int K3 = 3 * K;
    const long total = nrows << cslog2;
    for (long g = (long)blockIdx.x * blockDim.x + threadIdx.x; g < total;
         g += (long)gridDim.x * blockDim.x) {
        long r  = g >> cslog2;
        int col = (int)(g & ((1 << cslog2) - 1)) << 3;
        const float* sp = src + r * lds + col;
        float4 v0 = *(const float4*)sp;
        float4 v1 = *(const float4*)(sp + 4);
        float vv[8] = {v0.x, v0.y, v0.z, v0.w, v1.x, v1.y, v1.z, v1.w};
        union { __nv_bfloat16 b[8]; uint4 u; } H, L;
#pragma unroll
        for (int j = 0; j < 8; j++) {
            __nv_bfloat16 h = __float2bfloat16(vv[j]);
            H.b[j] = h;
            L.b[j] = __float2bfloat16(vv[j] - __bfloat162float(h));
        }
        __nv_bfloat16* d = dst + r * K3 + col;
        *(uint4*)d            = H.u;
        *(uint4*)(d + K)      = (mode == 0) ? L.u : H.u;
        *(uint4*)(d + 2 * K)  = (mode == 0) ? H.u : L.u;
    }
}

// =============================================================================
// HMMA GEMM: C[m,n] = sum_k A''[m,k]*B''[n,k] + bias[n]
// 128x128 tile, BK=32, 8 warps (32x64 each), 3-stage cp.async pipeline
// =============================================================================
__global__ __launch_bounds__(256)
void gemm_hmma(const __nv_bfloat16* __restrict__ Ap,
               const __nv_bfloat16* __restrict__ Bp,
               const float* __restrict__ bias,
               float* __restrict__ C, int K3)
{
    __shared__ __align__(16) __nv_bfloat16 sA[3][128 * 32];
    __shared__ __align__(16) __nv_bfloat16 sB[3][128 * 32];

    const int tid  = threadIdx.x;
    const int wid  = tid >> 5, lane = tid & 31;
    const int warpM = wid & 3, warpN = wid >> 2;
    const int m0 = blockIdx.y * 128, n0 = blockIdx.x * 128;
    const int nk = K3 >> 5;

    const uint32_t saA = smem_u32(&sA[0][0]);
    const uint32_t saB = smem_u32(&sB[0][0]);

    // per-thread load coordinates (2 x 16B per matrix per stage)
    const int lrow0 = tid >> 2;             // idx = tid       -> row, chunk
    const int lc0   = tid & 3;
    const int lrow1 = (tid + 256) >> 2;
    const int lc1   = (tid + 256) & 3;

    float acc[2][8][4];
#pragma unroll
    for (int a = 0; a < 2; a++)
#pragma unroll
        for (int b = 0; b < 8; b++)
#pragma unroll
            for (int c = 0; c < 4; c++) acc[a][b][c] = 0.f;

#define ISSUE(stage, kt)                                                         \
    do {                                                                         \
        uint32_t dA = saA + (stage) * 8192;                                      \
        uint32_t dB = saB + (stage) * 8192;                                      \
        cpasync16(dA + lrow0 * 64 + ((lc0 ^ (lrow0 & 3)) << 4),                  \
                  Ap + (size_t)(m0 + lrow0) * K3 + (kt) + lc0 * 8);              \
        cpasync16(dA + lrow1 * 64 + ((lc1 ^ (lrow1 & 3)) << 4),                  \
                  Ap + (size_t)(m0 + lrow1) * K3 + (kt) + lc1 * 8);              \
        cpasync16(dB + lrow0 * 64 + ((lc0 ^ (lrow0 & 3)) << 4),                  \
                  Bp + (size_t)(n0 + lrow0) * K3 + (kt) + lc0 * 8);              \
        cpasync16(dB + lrow1 * 64 + ((lc1 ^ (lrow1 & 3)) << 4),                  \
                  Bp + (size_t)(n0 + lrow1) * K3 + (kt) + lc1 * 8);              \
    } while (0)

    ISSUE(0, 0);  CP_COMMIT();
    ISSUE(1, 32); CP_COMMIT();

    const int g  = lane >> 3;     // ldmatrix quadrant
    const int lr = lane & 7;

    for (int i = 0; i < nk; i++) {
        CP_WAIT1();
        __syncthreads();
        const int st = i % 3;
        const uint32_t bA = saA + st * 8192;
        const uint32_t bB = saB + st * 8192;
#pragma unroll
        for (int kk = 0; kk < 2; kk++) {           // two k16 steps per chunk
            uint32_t afr[2][4], bfr[4][4];
#pragma unroll
            for (int mh = 0; mh < 2; mh++) {
                int row = warpM * 32 + mh * 16 + (g & 1) * 8 + lr;
                int ch  = (2 * kk + (g >> 1)) ^ (row & 3);
                ldsm4(afr[mh], bA + row * 64 + ch * 16);
            }
#pragma unroll
            for (int j = 0; j < 4; j++) {
                int row = warpN * 64 + j * 16 + (g >> 1) * 8 + lr;
                int ch  = (2 * kk + (g & 1)) ^ (row & 3);
                ldsm4(bfr[j], bB + row * 64 + ch * 16);
            }
#pragma unroll
            for (int mh = 0; mh < 2; mh++)
#pragma unroll
                for (int j = 0; j < 4; j++) {
                    mma_bf16(acc[mh][2 * j],     afr[mh], &bfr[j][0]);
                    mma_bf16(acc[mh][2 * j + 1], afr[mh], &bfr[j][2]);
                }
        }
        __syncthreads();
        if (i + 2 < nk) ISSUE((i + 2) % 3, (i + 2) * 32);
        CP_COMMIT();
    }
#undef ISSUE

    // epilogue: acc + bias -> C
#pragma unroll
    for (int mh = 0; mh < 2; mh++)
#pragma unroll
        for (int j = 0; j < 8; j++) {
            int row = m0 + warpM * 32 + mh * 16 + (lane >> 2);
            int col = n0 + warpN * 64 + j * 8 + (lane & 3) * 2;
            float b0 = bias[col], b1 = bias[col + 1];
            float2 v0 = {acc[mh][j][0] + b0, acc[mh][j][1] + b1};
            float2 v1 = {acc[mh][j][2] + b0, acc[mh][j][3] + b1};
            *(float2*)(C + (size_t)row * G4 + col)       = v0;
            *(float2*)(C + (size_t)(row + 8) * G4 + col) = v1;
        }
}

// =============================================================================
// Persistent FFMA recurrence (unchanged — known correct)
// =============================================================================
__device__ __forceinline__ void gridbarrier()
{
    __syncthreads();
    if (threadIdx.x == 0) {
        unsigned gen = *((volatile unsigned*)&g_gen);
        __threadfence();
        if (atomicAdd(&g_cnt, 1u) == NBLK - 1) {
            atomicExch(&g_cnt, 0u);
            __threadfence();
            atomicAdd(&g_gen, 1u);
        } else {
            while (*((volatile unsigned*)&g_gen) == gen) { }
        }
    }
    __syncthreads();
}
__device__ __forceinline__ float fsig(float x)  { return __fdividef(1.f, 1.f + __expf(-x)); }
__device__ __forceinline__ float ftanh(float x) { return 2.f * __fdividef(1.f, 1.f + __expf(-2.f * x)) - 1.f; }

#define WS_OFF 0
#define HS_OFF (WS_OFF + 1024*36)
#define GS_OFF (HS_OFF + 128*68)
#define CC_OFF (GS_OFF + 64*36)
#define SMEM_FLOATS (CC_OFF + 64*8)

__global__ __launch_bounds__(RT, 1)
void lstm_recur(const float* __restrict__ W, int ldw, int hoff,
                const float* __restrict__ Z,
                float* __restrict__ outSeq)
{
    extern __shared__ float smem[];
    float* Ws = smem + WS_OFF;
    float* hs = smem + HS_OFF;
    float* gs = smem + GS_OFF;
    float* cc = smem + CC_OFF;

    const int tid = threadIdx.x;
    const int blk = blockIdx.x;
    const int rg  = tid & 7;
    const int sg  = tid >> 3;

    for (int r = 0; r < 32; r++) {
        int gate = r >> 3, j = r & 7;
        const float* src = W + (size_t)(gate * HID + blk * 8 + j) * ldw + hoff;
        for (int k = tid * 4; k < HID; k += RT * 4) {
            float4 v = *(const float4*)(src + k);
            Ws[(k + 0) * 36 + r] = v.x; Ws[(k + 1) * 36 + r] = v.y;
            Ws[(k + 2) * 36 + r] = v.z; Ws[(k + 3) * 36 + r] = v.w;
        }
    }
    for (int i = tid; i < 64 * 8; i += RT) cc[i] = 0.f;
    for (int i = blk * 512 + tid; i < blk * 512 + 512; i += RT) g_Hping[i] = 0.f;
    __threadfence();
    gridbarrier();

    for (int t = 0; t < TT; t++) {
        const float* hin = g_Hping + (t & 1) * (HID * BSZ);
        float acc[4][4];
#pragma unroll
        for (int i = 0; i < 4; i++)
#pragma unroll
            for (int j = 0; j < 4; j++) acc[i][j] = 0.f;

        for (int kc = 0; kc < HID; kc += 128) {
            __syncthreads();
            for (int f = tid; f < 2048; f += RT) {
                int k  = f >> 4;
                int s4 = (f & 15) << 2;
                *(float4*)(hs + k * 68 + s4) =
                    *(const float4*)(hin + (size_t)(kc + k) * 64 + s4);
            }
            __syncthreads();
#pragma unroll 8
            for (int k = 0; k < 128; k++) {
                float4 h4 = *(const float4*)(hs + k * 68 + sg * 4);
                float4 w4 = *(const float4*)(Ws + (size_t)(kc + k) * 36 + rg * 4);
                acc[0][0] += h4.x * w4.x; acc[0][1] += h4.x * w4.y;
                acc[0][2] += h4.x * w4.z; acc[0][3] += h4.x * w4.w;
                acc[1][0] += h4.y * w4.x; acc[1][1] += h4.y * w4.y;
                acc[1][2] += h4.y * w4.z; acc[1][3] += h4.y * w4.w;
                acc[2][0] += h4.z * w4.x; acc[2][1] += h4.z * w4.y;
                acc[2][2] += h4.z * w4.z; acc[2][3] += h4.z * w4.w;
                acc[3][0] += h4.w * w4.x; acc[3][1] += h4.w * w4.y;
                acc[3][2] += h4.w * w4.z; acc[3][3] += h4.w * w4.w;
            }
        }
        __syncthreads();
#pragma unroll
        for (int si = 0; si < 4; si++)
#pragma unroll
            for (int ri = 0; ri < 4; ri++)
                gs[(sg * 4 + si) * 36 + rg * 4 + ri] = acc[si][ri];
        __syncthreads();

        float* hout = g_Hping + ((t + 1) & 1) * (HID * BSZ);
#pragma unroll
        for (int it = 0; it < 4; it++) {
            int cid = tid + RT * it;
            int s = cid >> 3, j = cid & 7;
            size_t row = (size_t)s * TT + t;
            const float* zp = Z + row * G4 + blk * 8 + j;
            float zi = zp[0]        + gs[s * 36 +  0 + j];
            float zf = zp[HID]      + gs[s * 36 +  8 + j];
            float zo = zp[2 * HID]  + gs[s * 36 + 16 + j];
            float zg = zp[3 * HID]  + gs[s * 36 + 24 + j];
            float c  = cc[s * 8 + j];
            float cn = fsig(zf) * c + fsig(zi) * ftanh(zg);
            float hn = fsig(zo) * ftanh(cn);
            cc[s * 8 + j] = cn;
            int u = blk * 8 + j;
            outSeq[row * HID + u] = hn;
            hout[(size_t)u * 64 + s] = hn;
        }
        __threadfence();
        gridbarrier();
    }
}

// =============================================================================
extern "C" void kernel_launch(void* const* d_in, const int* in_sizes, int n_in,
                              void* d_out, int out_size)
{
    const float* x  = (const float*)d_in[0];
    const float* W0 = (const float*)d_in[1];
    const float* b0 = (const float*)d_in[2];
    const float* W1 = (const float*)d_in[3];
    const float* b1 = (const float*)d_in[4];
    float* out = (float*)d_out;

    float *pZ = nullptr, *pH0 = nullptr;
    __nv_bfloat16 *pA = nullptr, *pB = nullptr;
    cudaGetSymbolAddress((void**)&pZ,  g_Z);
    cudaGetSymbolAddress((void**)&pH0, g_H0);
    cudaGetSymbolAddress((void**)&pA,  g_Apack);
    cudaGetSymbolAddress((void**)&pB,  g_Bpack);

    cudaFuncSetAttribute(lstm_recur, cudaFuncAttributeMaxDynamicSharedMemorySize,
                         SMEM_FLOATS * sizeof(float));

    dim3 gg(NT, MT);

    // ---- layer 0: Z = bf16x3-GEMM(x, W0_x) + b0   (K=512, cslog2=6)
    pack3<<<1024, 256>>>(x,  DD,       6, MROWS, pA, 0);
    pack3<<<256,  256>>>(W0, DD + HID, 6, G4,    pB, 1);
    gemm_hmma<<<gg, 256>>>(pA, pB, b0, pZ, 3 * DD);
    lstm_recur<<<NBLK, RT, SMEM_FLOATS * sizeof(float)>>>(W0, DD + HID, DD, pZ, pH0);

    // ---- layer 1   (K=1024, cslog2=7)
    pack3<<<1024, 256>>>(pH0, HID,     7, MROWS, pA, 0);
    pack3<<<256,  256>>>(W1,  2 * HID, 7, G4,    pB, 1);
    gemm_hmma<<<gg, 256>>>(pA, pB, b1, pZ, 3 * HID);
    lstm_recur<<<NBLK, RT, SMEM_FLOATS * sizeof(float)>>>(W1, 2 * HID, HID, pZ, out);
}

// round 6
// speedup vs baseline: 1.8972x; 1.7028x over previous
#include <cuda_runtime.h>
#include <cuda_bf16.h>
#include <cstdint>

#define BSZ   64
#define TT    512
#define DD    512
#define HID   1024
#define G4    4096
#define MROWS (BSZ*TT)             // 32768
#define NBLK  128
#define MT    (MROWS/128)          // 256 M tiles
#define NT    (G4/128)             // 32  N tiles
#define PLANE 65536                // 64 x 1024 bf16 elements per plane

// ---------------- device scratch -------------------------------------------
__device__ __align__(16) float    g_Z[(size_t)MROWS * G4];      // 512 MB
__device__ __align__(16) float    g_H0[(size_t)MROWS * HID];    // 128 MB
__device__ __align__(16) __nv_bfloat16 g_hbf[4 * PLANE];        // ping x {hi,lo}
__device__ int g_flags[2][NBLK];
__device__ __align__(16) __nv_bfloat16 g_Apack[(size_t)MROWS * 3 * HID]; // 201 MB
__device__ __align__(16) __nv_bfloat16 g_Bpack[(size_t)G4 * 3 * HID];    // 25 MB

// ---------------- PTX helpers (family-portable) ------------------------------
__device__ __forceinline__ uint32_t smem_u32(const void* p)
{
    uint32_t a;
    asm("{ .reg .u64 t; cvta.to.shared.u64 t, %1; cvt.u32.u64 %0, t; }"
        : "=r"(a) : "l"(p));
    return a;
}
__device__ __forceinline__ void cpasync16(uint32_t dst, const void* src)
{
    asm volatile("cp.async.cg.shared.global [%0], [%1], 16;"
                 :: "r"(dst), "l"(src));
}
#define CP_COMMIT() asm volatile("cp.async.commit_group;")
#define CP_WAIT1()  asm volatile("cp.async.wait_group 1;")
#define CP_WAIT0()  asm volatile("cp.async.wait_group 0;")

__device__ __forceinline__ void ldsm4(uint32_t* r, uint32_t addr)
{
    asm volatile("ldmatrix.sync.aligned.m8n8.x4.shared.b16 {%0,%1,%2,%3}, [%4];"
                 : "=r"(r[0]), "=r"(r[1]), "=r"(r[2]), "=r"(r[3]) : "r"(addr));
}
__device__ __forceinline__ void mma_bf16(float* c, const uint32_t* a,
                                         const uint32_t* b)
{
    asm volatile(
        "mma.sync.aligned.m16n8k16.row.col.f32.bf16.bf16.f32 "
        "{%0,%1,%2,%3}, {%4,%5,%6,%7}, {%8,%9}, {%0,%1,%2,%3};"
        : "+f"(c[0]), "+f"(c[1]), "+f"(c[2]), "+f"(c[3])
        : "r"(a[0]), "r"(a[1]), "r"(a[2]), "r"(a[3]), "r"(b[0]), "r"(b[1]));
}

// =============================================================================
// pack3: fp32 -> bf16x3 row-major panels (unchanged from R5)
// =============================================================================
__global__ void pack3(const float* __restrict__ src, int lds, int cslog2,
                      long nrows, __nv_bfloat16* __restrict__ dst, int mode)
{
    const int K = 8 << cslog2;
    const int K3 = 3 * K;
    const long total = nrows << cslog2;
    for (long g = (long)blockIdx.x * blockDim.x + threadIdx.x; g < total;
         g += (long)gridDim.x * blockDim.x) {
        long r  = g >> cslog2;
        int col = (int)(g & ((1 << cslog2) - 1)) << 3;
        const float* sp = src + r * lds + col;
        float4 v0 = *(const float4*)sp;
        float4 v1 = *(const float4*)(sp + 4);
        float vv[8] = {v0.x, v0.y, v0.z, v0.w, v1.x, v1.y, v1.z, v1.w};
        union { __nv_bfloat16 b[8]; uint4 u; } H, L;
#pragma unroll
        for (int j = 0; j < 8; j++) {
            __nv_bfloat16 h = __float2bfloat16(vv[j]);
            H.b[j] = h;
            L.b[j] = __float2bfloat16(vv[j] - __bfloat162float(h));
        }
        __nv_bfloat16* d = dst + r * K3 + col;
        *(uint4*)d            = H.u;
        *(uint4*)(d + K)      = (mode == 0) ? L.u : H.u;
        *(uint4*)(d + 2 * K)  = (mode == 0) ? H.u : L.u;
    }
}

// =============================================================================
// HMMA GEMM for input projections (unchanged from R5 — known correct)
// =============================================================================
__global__ __launch_bounds__(256)
void gemm_hmma(const __nv_bfloat16* __restrict__ Ap,
               const __nv_bfloat16* __restrict__ Bp,
               const float* __restrict__ bias,
               float* __restrict__ C, int K3)
{
    __shared__ __align__(16) __nv_bfloat16 sA[3][128 * 32];
    __shared__ __align__(16) __nv_bfloat16 sB[3][128 * 32];

    const int tid  = threadIdx.x;
    const int wid  = tid >> 5, lane = tid & 31;
    const int warpM = wid & 3, warpN = wid >> 2;
    const int m0 = blockIdx.y * 128, n0 = blockIdx.x * 128;
    const int nk = K3 >> 5;

    const uint32_t saA = smem_u32(&sA[0][0]);
    const uint32_t saB = smem_u32(&sB[0][0]);

    const int lrow0 = tid >> 2;
    const int lc0   = tid & 3;
    const int lrow1 = (tid + 256) >> 2;
    const int lc1   = (tid + 256) & 3;

    float acc[2][8][4];
#pragma unroll
    for (int a = 0; a < 2; a++)
#pragma unroll
        for (int b = 0; b < 8; b++)
#pragma unroll
            for (int c = 0; c < 4; c++) acc[a][b][c] = 0.f;

#define ISSUE(stage, kt)                                                         \
    do {                                                                         \
        uint32_t dA = saA + (stage) * 8192;                                      \
        uint32_t dB = saB + (stage) * 8192;                                      \
        cpasync16(dA + lrow0 * 64 + ((lc0 ^ (lrow0 & 3)) << 4),                  \
                  Ap + (size_t)(m0 + lrow0) * K3 + (kt) + lc0 * 8);              \
        cpasync16(dA + lrow1 * 64 + ((lc1 ^ (lrow1 & 3)) << 4),                  \
                  Ap + (size_t)(m0 + lrow1) * K3 + (kt) + lc1 * 8);              \
        cpasync16(dB + lrow0 * 64 + ((lc0 ^ (lrow0 & 3)) << 4),                  \
                  Bp + (size_t)(n0 + lrow0) * K3 + (kt) + lc0 * 8);              \
        cpasync16(dB + lrow1 * 64 + ((lc1 ^ (lrow1 & 3)) << 4),                  \
                  Bp + (size_t)(n0 + lrow1) * K3 + (kt) + lc1 * 8);              \
    } while (0)

    ISSUE(0, 0);  CP_COMMIT();
    ISSUE(1, 32); CP_COMMIT();

    const int g  = lane >> 3;
    const int lr = lane & 7;

    for (int i = 0; i < nk; i++) {
        CP_WAIT1();
        __syncthreads();
        const int st = i % 3;
        const uint32_t bA = saA + st * 8192;
        const uint32_t bB = saB + st * 8192;
#pragma unroll
        for (int kk = 0; kk < 2; kk++) {
            uint32_t afr[2][4], bfr[4][4];
#pragma unroll
            for (int mh = 0; mh < 2; mh++) {
                int row = warpM * 32 + mh * 16 + (g & 1) * 8 + lr;
                int ch  = (2 * kk + (g >> 1)) ^ (row & 3);
                ldsm4(afr[mh], bA + row * 64 + ch * 16);
            }
#pragma unroll
            for (int j = 0; j < 4; j++) {
                int row = warpN * 64 + j * 16 + (g >> 1) * 8 + lr;
                int ch  = (2 * kk + (g & 1)) ^ (row & 3);
                ldsm4(bfr[j], bB + row * 64 + ch * 16);
            }
#pragma unroll
            for (int mh = 0; mh < 2; mh++)
#pragma unroll
                for (int j = 0; j < 4; j++) {
                    mma_bf16(acc[mh][2 * j],     afr[mh], &bfr[j][0]);
                    mma_bf16(acc[mh][2 * j + 1], afr[mh], &bfr[j][2]);
                }
        }
        __syncthreads();
        if (i + 2 < nk) ISSUE((i + 2) % 3, (i + 2) * 32);
        CP_COMMIT();
    }
#undef ISSUE

#pragma unroll
    for (int mh = 0; mh < 2; mh++)
#pragma unroll
        for (int j = 0; j < 8; j++) {
            int row = m0 + warpM * 32 + mh * 16 + (lane >> 2);
            int col = n0 + warpN * 64 + j * 8 + (lane & 3) * 2;
            float b0 = bias[col], b1 = bias[col + 1];
            float2 v0 = {acc[mh][j][0] + b0, acc[mh][j][1] + b1};
            float2 v1 = {acc[mh][j][2] + b0, acc[mh][j][3] + b1};
            *(float2*)(C + (size_t)row * G4 + col)       = v0;
            *(float2*)(C + (size_t)(row + 8) * G4 + col) = v1;
        }
}

// =============================================================================
// Persistent HMMA recurrence.
// 128 blocks, 256 threads. Block owns 8 hidden units -> N = 32 cols (4 gates).
// Whi/Wlo (32x1024 bf16 each) cached swizzled in smem for all 512 steps.
// h exchanged per step as bf16 hi+lo planes in gmem, streamed via cp.async.
// acc = Ahi*Whi + Alo*Whi + Ahi*Wlo  (bf16x3, fp32 accumulate).
// =============================================================================
__device__ __forceinline__ float fsig(float x)  { return __fdividef(1.f, 1.f + __expf(-x)); }
__device__ __forceinline__ float ftanh(float x) { return 2.f * __fdividef(1.f, 1.f + __expf(-2.f * x)) - 1.f; }

// smem byte layout
#define R_WHI 0                         // 65536
#define R_WLO 65536                     // 65536
#define R_AB  131072                    // 2 x 32768 (double-buffered A chunks)
#define R_GS  196608                    // 64*36*4 = 9216
#define R_CC  205824                    // 512*4
#define R_SMEM 207872

__device__ __forceinline__ void flagbar(volatile int* f, int blk, int tid, int target)
{
    __threadfence();
    __syncthreads();
    if (tid == 0) f[blk] = target;
    if (tid < NBLK) { while (f[tid] < target) { } }
    __syncthreads();
}

__global__ __launch_bounds__(256, 1)
void lstm_recur(const float* __restrict__ W, int ldw, int hoff,
                const float* __restrict__ Z,
                float* __restrict__ outSeq, int sel)
{
    extern __shared__ char sm[];
    float* gs = (float*)(sm + R_GS);
    float* cc = (float*)(sm + R_CC);

    const int tid = threadIdx.x, blk = blockIdx.x;
    const int lane = tid & 31, wid = tid >> 5;
    const int warpM = wid & 3, warpN = wid >> 2;
    const int g = lane >> 3, lr = lane & 7;

    volatile int* fSelf  = (volatile int*)g_flags[sel];
    volatile int* fOther = (volatile int*)g_flags[sel ^ 1];
    if (tid == 0) fOther[blk] = 0;        // reset the other launch's flags

    const uint32_t saW = smem_u32(sm);
    const uint32_t saA = saW + R_AB;

    // ---- prologue: load recurrent weights, convert to swizzled bf16 hi/lo
    for (int idx = tid; idx < 32 * 1024; idx += 256) {
        int r = idx >> 10, k = idx & 1023;
        float v = W[(size_t)((r >> 3) * HID + blk * 8 + (r & 7)) * ldw + hoff + k];
        __nv_bfloat16 h = __float2bfloat16(v);
        __nv_bfloat16 l = __float2bfloat16(v - __bfloat162float(h));
        uint32_t off = r * 2048 + ((((k >> 3) ^ (r & 7)) << 4)) + (k & 7) * 2;
        *(__nv_bfloat16*)(sm + R_WHI + off) = h;
        *(__nv_bfloat16*)(sm + R_WLO + off) = l;
    }
    for (int i = tid; i < 512; i += 256) cc[i] = 0.f;
    // zero our h slice in ping 0 (both planes)
    for (int i = tid; i < 1024; i += 256) {
        int plane = i >> 9, s = (i >> 3) & 63, j = i & 7;
        g_hbf[(size_t)plane * PLANE + (size_t)s * 1024 + blk * 8 + j] = __float2bfloat16(0.f);
    }
    flagbar(fSelf, blk, tid, 1);

    // per-warp invariant fragment addressing
    const int arow = warpM * 16 + (g & 1) * 8 + lr;     // 0..63
    const int brow = warpN * 16 + (g >> 1) * 8 + lr;    // 0..31
    const uint32_t aBase = saA + arow * 512;
    const int aXor = arow & 7, bXor = brow & 7;
    const int aC0 = g >> 1, bC0 = g & 1;
    const uint32_t bHi = saW + R_WHI + brow * 2048;
    const uint32_t bLo = saW + R_WLO + brow * 2048;

    for (int t = 0; t < TT; t++) {
        const __nv_bfloat16* hin = g_hbf + (size_t)(t & 1) * 2 * PLANE;

        float acc[2][4];
#pragma unroll
        for (int a = 0; a < 2; a++)
#pragma unroll
            for (int c = 0; c < 4; c++) acc[a][c] = 0.f;

#define ISSUEA(j)                                                                \
    do {                                                                         \
        const __nv_bfloat16* src = hin + ((j) >> 2) * PLANE + ((j) & 3) * 256;   \
        uint32_t dst = saA + ((j) & 1) * 32768;                                  \
        _Pragma("unroll")                                                        \
        for (int q = 0; q < 8; q++) {                                            \
            int f = tid + 256 * q;                                               \
            int s = f >> 5, c = f & 31;                                          \
            cpasync16(dst + s * 512 + ((c ^ (s & 7)) << 4),                      \
                      src + (size_t)s * 1024 + c * 8);                           \
        }                                                                        \
    } while (0)

        ISSUEA(0);
        CP_COMMIT();
        for (int i = 0; i < 8; i++) {
            if (i < 7) { ISSUEA(i + 1); CP_COMMIT(); CP_WAIT1(); }
            else       { CP_WAIT0(); }
            __syncthreads();
            const uint32_t ab = aBase + (i & 1) * 32768;
            const int pass = i >> 2, st = i & 3;
#pragma unroll
            for (int kk = 0; kk < 16; kk++) {
                const int k16g = st * 16 + kk;
                uint32_t afr[4], bh[4];
                ldsm4(afr, ab + (((2 * kk + aC0) ^ aXor) << 4));
                const uint32_t bcix = ((2 * k16g + bC0) ^ bXor) << 4;
                ldsm4(bh, bHi + bcix);
                mma_bf16(acc[0], afr, &bh[0]);
                mma_bf16(acc[1], afr, &bh[2]);
                if (pass == 0) {
                    uint32_t bl[4];
                    ldsm4(bl, bLo + bcix);
                    mma_bf16(acc[0], afr, &bl[0]);
                    mma_bf16(acc[1], afr, &bl[2]);
                }
            }
            __syncthreads();
        }
#undef ISSUEA

        // ---- dump acc -> gs [64 s][36]
#pragma unroll
        for (int t8 = 0; t8 < 2; t8++) {
            int n  = warpN * 16 + t8 * 8 + (lane & 3) * 2;
            int s0 = warpM * 16 + (lane >> 2);
            gs[s0 * 36 + n]           = acc[t8][0];
            gs[s0 * 36 + n + 1]       = acc[t8][1];
            gs[(s0 + 8) * 36 + n]     = acc[t8][2];
            gs[(s0 + 8) * 36 + n + 1] = acc[t8][3];
        }
        __syncthreads();

        // ---- gate math: 512 cells, 2 per thread
        __nv_bfloat16* ho = g_hbf + (size_t)((t + 1) & 1) * 2 * PLANE;
#pragma unroll
        for (int it = 0; it < 2; it++) {
            int cid = tid + 256 * it;           // = s*8 + j
            int s = cid >> 3, j = cid & 7;
            size_t row = (size_t)s * TT + t;
            const float* zp = Z + row * G4 + blk * 8 + j;
            float zi = zp[0]       + gs[s * 36 +  0 + j];
            float zf = zp[HID]     + gs[s * 36 +  8 + j];
            float zo = zp[2 * HID] + gs[s * 36 + 16 + j];
            float zg = zp[3 * HID] + gs[s * 36 + 24 + j];
            float c  = cc[cid];
            float cn = fsig(zf) * c + fsig(zi) * ftanh(zg);
            float hn = fsig(zo) * ftanh(cn);
            cc[cid] = cn;
            int u = blk * 8 + j;
            outSeq[row * HID + u] = hn;
            __nv_bfloat16 hh = __float2bfloat16(hn);
            __nv_bfloat16 hl = __float2bfloat16(hn - __bfloat162float(hh));
            ho[(size_t)s * 1024 + u]         = hh;
            ho[PLANE + (size_t)s * 1024 + u] = hl;
        }

        if (t < TT - 1) flagbar(fSelf, blk, tid, t + 2);
    }
}

// =============================================================================
extern "C" void kernel_launch(void* const* d_in, const int* in_sizes, int n_in,
                              void* d_out, int out_size)
{
    const float* x  = (const float*)d_in[0];
    const float* W0 = (const float*)d_in[1];
    const float* b0 = (const float*)d_in[2];
    const float* W1 = (const float*)d_in[3];
    const float* b1 = (const float*)d_in[4];
    float* out = (float*)d_out;

    float *pZ = nullptr, *pH0 = nullptr;
    __nv_bfloat16 *pA = nullptr, *pB = nullptr;
    cudaGetSymbolAddress((void**)&pZ,  g_Z);
    cudaGetSymbolAddress((void**)&pH0, g_H0);
    cudaGetSymbolAddress((void**)&pA,  g_Apack);
    cudaGetSymbolAddress((void**)&pB,  g_Bpack);

    cudaFuncSetAttribute(lstm_recur, cudaFuncAttributeMaxDynamicSharedMemorySize,
                         R_SMEM);

    dim3 gg(NT, MT);

    // ---- layer 0: Z = bf16x3-GEMM(x, W0_x) + b0   (K=512)
    pack3<<<1024, 256>>>(x,  DD,       6, MROWS, pA, 0);
    pack3<<<256,  256>>>(W0, DD + HID, 6, G4,    pB, 1);
    gemm_hmma<<<gg, 256>>>(pA, pB, b0, pZ, 3 * DD);
    lstm_recur<<<NBLK, 256, R_SMEM>>>(W0, DD + HID, DD, pZ, pH0, 0);

    // ---- layer 1   (K=1024)
    pack3<<<1024, 256>>>(pH0, HID,     7, MROWS, pA, 0);
    pack3<<<256,  256>>>(W1,  2 * HID, 7, G4,    pB, 1);
    gemm_hmma<<<gg, 256>>>(pA, pB, b1, pZ, 3 * HID);
    lstm_recur<<<NBLK, 256, R_SMEM>>>(W1, 2 * HID, HID, pZ, out, 1);
}

// round 8
// speedup vs baseline: 2.3791x; 1.2540x over previous
#include <cuda_runtime.h>
#include <cuda_bf16.h>
#include <cstdint>

#define BSZ   64
#define TT    512
#define DD    512
#define HID   1024
#define G4    4096
#define MROWS (BSZ*TT)             // 32768
#define NBLK  128
#define MT    (MROWS/128)          // 256 M tiles
#define NT    (G4/128)             // 32  N tiles
#define PLANE 65536                // 64 x 1024 bf16 elements per plane

// ---------------- device scratch -------------------------------------------
__device__ __align__(16) float    g_Z[(size_t)MROWS * G4];      // 512 MB
__device__ __align__(16) float    g_H0[(size_t)MROWS * HID];    // 128 MB
__device__ __align__(16) __nv_bfloat16 g_hbf[4 * PLANE];        // ping-pong h (hi)
__device__ int g_flags[2][NBLK];
__device__ __align__(16) __nv_bfloat16 g_Apack[(size_t)MROWS * 3 * HID]; // 201 MB
__device__ __align__(16) __nv_bfloat16 g_Bpack[(size_t)G4 * 3 * HID];    // 25 MB

// ---------------- PTX helpers (family-portable) ------------------------------
__device__ __forceinline__ uint32_t smem_u32(const void* p)
{
    uint32_t a;
    asm("{ .reg .u64 t; cvta.to.shared.u64 t, %1; cvt.u32.u64 %0, t; }"
        : "=r"(a) : "l"(p));
    return a;
}
__device__ __forceinline__ void cpasync16(uint32_t dst, const void* src)
{
    asm volatile("cp.async.cg.shared.global [%0], [%1], 16;"
                 :: "r"(dst), "l"(src));
}
#define CP_COMMIT() asm volatile("cp.async.commit_group;")
#define CP_WAIT1()  asm volatile("cp.async.wait_group 1;")
#define CP_WAIT0()  asm volatile("cp.async.wait_group 0;")

__device__ __forceinline__ void ldsm4(uint32_t* r, uint32_t addr)
{
    asm volatile("ldmatrix.sync.aligned.m8n8.x4.shared.b16 {%0,%1,%2,%3}, [%4];"
                 : "=r"(r[0]), "=r"(r[1]), "=r"(r[2]), "=r"(r[3]) : "r"(addr));
}
__device__ __forceinline__ void mma_bf16(float* c, const uint32_t* a,
                                         const uint32_t* b)
{
    asm volatile(
        "mma.sync.aligned.m16n8k16.row.col.f32.bf16.bf16.f32 "
        "{%0,%1,%2,%3}, {%4,%5,%6,%7}, {%8,%9}, {%0,%1,%2,%3};"
        : "+f"(c[0]), "+f"(c[1]), "+f"(c[2]), "+f"(c[3])
        : "r"(a[0]), "r"(a[1]), "r"(a[2]), "r"(a[3]), "r"(b[0]), "r"(b[1]));
}

// =============================================================================
// pack3: fp32 -> bf16x3 row-major panels (unchanged)
// =============================================================================
__global__ void pack3(const float* __restrict__ src, int lds, int cslog2,
                      long nrows, __nv_bfloat16* __restrict__ dst, int mode)
{
    const int K = 8 << cslog2;
    const int K3 = 3 * K;
    const long total = nrows << cslog2;
    for (long g = (long)blockIdx.x * blockDim.x + threadIdx.x; g < total;
         g += (long)gridDim.x * blockDim.x) {
        long r  = g >> cslog2;
        int col = (int)(g & ((1 << cslog2) - 1)) << 3;
        const float* sp = src + r * lds + col;
        float4 v0 = *(const float4*)sp;
        float4 v1 = *(const float4*)(sp + 4);
        float vv[8] = {v0.x, v0.y, v0.z, v0.w, v1.x, v1.y, v1.z, v1.w};
        union { __nv_bfloat16 b[8]; uint4 u; } H, L;
#pragma unroll
        for (int j = 0; j < 8; j++) {
            __nv_bfloat16 h = __float2bfloat16(vv[j]);
            H.b[j] = h;
            L.b[j] = __float2bfloat16(vv[j] - __bfloat162float(h));
        }
        __nv_bfloat16* d = dst + r * K3 + col;
        *(uint4*)d            = H.u;
        *(uint4*)(d + K)      = (mode == 0) ? L.u : H.u;
        *(uint4*)(d + 2 * K)  = (mode == 0) ? H.u : L.u;
    }
}

// =============================================================================
// HMMA GEMM for input projections (unchanged — known correct)
// =============================================================================
__global__ __launch_bounds__(256)
void gemm_hmma(const __nv_bfloat16* __restrict__ Ap,
               const __nv_bfloat16* __restrict__ Bp,
               const float* __restrict__ bias,
               float* __restrict__ C, int K3)
{
    __shared__ __align__(16) __nv_bfloat16 sA[3][128 * 32];
    __shared__ __align__(16) __nv_bfloat16 sB[3][128 * 32];

    const int tid  = threadIdx.x;
    const int wid  = tid >> 5, lane = tid & 31;
    const int warpM = wid & 3, warpN = wid >> 2;
    const int m0 = blockIdx.y * 128, n0 = blockIdx.x * 128;
    const int nk = K3 >> 5;

    const uint32_t saA = smem_u32(&sA[0][0]);
    const uint32_t saB = smem_u32(&sB[0][0]);

    const int lrow0 = tid >> 2;
    const int lc0   = tid & 3;
    const int lrow1 = (tid + 256) >> 2;
    const int lc1   = (tid + 256) & 3;

    float acc[2][8][4];
#pragma unroll
    for (int a = 0; a < 2; a++)
#pragma unroll
        for (int b = 0; b < 8; b++)
#pragma unroll
            for (int c = 0; c < 4; c++) acc[a][b][c] = 0.f;

#define ISSUE(stage, kt)                                                         \
    do {                                                                         \
        uint32_t dA = saA + (stage) * 8192;                                      \
        uint32_t dB = saB + (stage) * 8192;                                      \
        cpasync16(dA + lrow0 * 64 + ((lc0 ^ (lrow0 & 3)) << 4),                  \
                  Ap + (size_t)(m0 + lrow0) * K3 + (kt) + lc0 * 8);              \
        cpasync16(dA + lrow1 * 64 + ((lc1 ^ (lrow1 & 3)) << 4),                  \
                  Ap + (size_t)(m0 + lrow1) * K3 + (kt) + lc1 * 8);              \
        cpasync16(dB + lrow0 * 64 + ((lc0 ^ (lrow0 & 3)) << 4),                  \
                  Bp + (size_t)(n0 + lrow0) * K3 + (kt) + lc0 * 8);              \
        cpasync16(dB + lrow1 * 64 + ((lc1 ^ (lrow1 & 3)) << 4),                  \
                  Bp + (size_t)(n0 + lrow1) * K3 + (kt) + lc1 * 8);              \
    } while (0)

    ISSUE(0, 0);  CP_COMMIT();
    ISSUE(1, 32); CP_COMMIT();

    const int g  = lane >> 3;
    const int lr = lane & 7;

    for (int i = 0; i < nk; i++) {
        CP_WAIT1();
        __syncthreads();
        const int st = i % 3;
        const uint32_t bA = saA + st * 8192;
        const uint32_t bB = saB + st * 8192;
#pragma unroll
        for (int kk = 0; kk < 2; kk++) {
            uint32_t afr[2][4], bfr[4][4];
#pragma unroll
            for (int mh = 0; mh < 2; mh++) {
                int row = warpM * 32 + mh * 16 + (g & 1) * 8 + lr;
                int ch  = (2 * kk + (g >> 1)) ^ (row & 3);
                ldsm4(afr[mh], bA + row * 64 + ch * 16);
            }
#pragma unroll
            for (int j = 0; j < 4; j++) {
                int row = warpN * 64 + j * 16 + (g >> 1) * 8 + lr;
                int ch  = (2 * kk + (g & 1)) ^ (row & 3);
                ldsm4(bfr[j], bB + row * 64 + ch * 16);
            }
#pragma unroll
            for (int mh = 0; mh < 2; mh++)
#pragma unroll
                for (int j = 0; j < 4; j++) {
                    mma_bf16(acc[mh][2 * j],     afr[mh], &bfr[j][0]);
                    mma_bf16(acc[mh][2 * j + 1], afr[mh], &bfr[j][2]);
                }
        }
        __syncthreads();
        if (i + 2 < nk) ISSUE((i + 2) % 3, (i + 2) * 32);
        CP_COMMIT();
    }
#undef ISSUE

#pragma unroll
    for (int mh = 0; mh < 2; mh++)
#pragma unroll
        for (int j = 0; j < 8; j++) {
            int row = m0 + warpM * 32 + mh * 16 + (lane >> 2);
            int col = n0 + warpN * 64 + j * 8 + (lane & 3) * 2;
            float b0 = bias[col], b1 = bias[col + 1];
            float2 v0 = {acc[mh][j][0] + b0, acc[mh][j][1] + b1};
            float2 v1 = {acc[mh][j][2] + b0, acc[mh][j][3] + b1};
            *(float2*)(C + (size_t)row * G4 + col)       = v0;
            *(float2*)(C + (size_t)(row + 8) * G4 + col) = v1;
        }
}

// =============================================================================
// Persistent HMMA recurrence, v2:
//   acc = Ahi*Whi + Ahi*Wlo (A_lo term dropped)
//   4 A chunks (hi plane only), double-buffered, prefetch-before-compute
//   Z staged via cp.async issued the step before (latency fully hidden)
// =============================================================================
__device__ __forceinline__ float fsig(float x)  { return __fdividef(1.f, 1.f + __expf(-x)); }
__device__ __forceinline__ float ftanh(float x) { return 2.f * __fdividef(1.f, 1.f + __expf(-2.f * x)) - 1.f; }

// smem byte layout
#define R_WHI 0                         // 65536
#define R_WLO 65536                     // 65536
#define R_AB  131072                    // 2 x 32768 double-buffered A chunks
#define R_ZS  196608                    // 64*40*4 = 10240 staged Z
#define R_GS  206848                    // 64*36*4 = 9216
#define R_CC  216064                    // 512*4
#define R_SMEM 218112

__device__ __forceinline__ void flagbar(volatile int* f, int blk, int tid, int target)
{
    __threadfence();
    __syncthreads();
    if (tid == 0) f[blk] = target;
    if (tid < NBLK) { while (f[tid] < target) { } }
    __syncthreads();
}

__global__ __launch_bounds__(256, 1)
void lstm_recur(const float* __restrict__ W, int ldw, int hoff,
                const float* __restrict__ Z,
                float* __restrict__ outSeq, int sel)
{
    extern __shared__ char sm[];
    float* zs = (float*)(sm + R_ZS);
    float* gs = (float*)(sm + R_GS);
    float* cc = (float*)(sm + R_CC);

    const int tid = threadIdx.x, blk = blockIdx.x;
    const int lane = tid & 31, wid = tid >> 5;
    const int warpM = wid & 3, warpN = wid >> 2;
    const int g = lane >> 3, lr = lane & 7;

    volatile int* fSelf  = (volatile int*)g_flags[sel];
    volatile int* fOther = (volatile int*)g_flags[sel ^ 1];
    if (tid == 0) fOther[blk] = 0;

    const uint32_t saW = smem_u32(sm);
    const uint32_t saA = saW + R_AB;
    const uint32_t saZ = saW + R_ZS;

    // ---- prologue: recurrent weights -> swizzled bf16 hi/lo in smem
    for (int idx = tid; idx < 32 * 1024; idx += 256) {
        int r = idx >> 10, k = idx & 1023;
        float v = W[(size_t)((r >> 3) * HID + blk * 8 + (r & 7)) * ldw + hoff + k];
        __nv_bfloat16 h = __float2bfloat16(v);
        __nv_bfloat16 l = __float2bfloat16(v - __bfloat162float(h));
        uint32_t off = r * 2048 + ((((k >> 3) ^ (r & 7)) << 4)) + (k & 7) * 2;
        *(__nv_bfloat16*)(sm + R_WHI + off) = h;
        *(__nv_bfloat16*)(sm + R_WLO + off) = l;
    }
    for (int i = tid; i < 512; i += 256) cc[i] = 0.f;
    // zero our h slice in ping 0 (hi plane only)
    for (int i = tid; i < 512; i += 256) {
        int s = i >> 3, j = i & 7;
        g_hbf[(size_t)s * 1024 + blk * 8 + j] = __float2bfloat16(0.f);
    }
    // prefetch Z(0): piece = (s, gate) = tid
    {
        int s = tid >> 2, gt = tid & 3;
        const float* src = Z + ((size_t)s * TT + 0) * G4 + gt * HID + blk * 8;
        uint32_t dst = saZ + s * 160 + gt * 32;
        cpasync16(dst,      src);
        cpasync16(dst + 16, src + 4);
    }
    CP_COMMIT();
    flagbar(fSelf, blk, tid, 1);

    // per-warp invariant fragment addressing
    const int arow = warpM * 16 + (g & 1) * 8 + lr;     // batch row 0..63
    const int brow = warpN * 16 + (g >> 1) * 8 + lr;    // gate col 0..31
    const uint32_t aBase = saA + arow * 512;
    const int aXor = arow & 7, bXor = brow & 7;
    const int aC0 = g >> 1, bC0 = g & 1;
    const uint32_t bHi = saW + R_WHI + brow * 2048;
    const uint32_t bLo = saW + R_WLO + brow * 2048;

    for (int t = 0; t < TT; t++) {
        const __nv_bfloat16* hin = g_hbf + (size_t)(t & 1) * 2 * PLANE;

        float acc[2][4];
#pragma unroll
        for (int a = 0; a < 2; a++)
#pragma unroll
            for (int c = 0; c < 4; c++) acc[a][c] = 0.f;

#define ISSUEA(j)                                                                \
    do {                                                                         \
        const __nv_bfloat16* src = hin + (j) * 256;                              \
        uint32_t dst = saA + ((j) & 1) * 32768;                                  \
        _Pragma("unroll")                                                        \
        for (int q = 0; q < 8; q++) {                                            \
            int f = tid + 256 * q;                                               \
            int s = f >> 5, c = f & 31;                                          \
            cpasync16(dst + s * 512 + ((c ^ (s & 7)) << 4),                      \
                      src + (size_t)s * 1024 + c * 8);                           \
        }                                                                        \
        CP_COMMIT();                                                             \
    } while (0)

        ISSUEA(0);
#pragma unroll
        for (int i = 0; i < 4; i++) {
            CP_WAIT0();                    // A_i ready (Z long since done)
            __syncthreads();
            if (i < 3) ISSUEA(i + 1);      // overlap load(i+1) with compute(i)
            const uint32_t ab = aBase + (i & 1) * 32768;
#pragma unroll
            for (int kk = 0; kk < 16; kk++) {
                const int k16g = i * 16 + kk;
                uint32_t afr[4], bh[4], bl[4];
                ldsm4(afr, ab + (((2 * kk + aC0) ^ aXor) << 4));
                const uint32_t bcix = ((2 * k16g + bC0) ^ bXor) << 4;
                ldsm4(bh, bHi + bcix);
                ldsm4(bl, bLo + bcix);
                mma_bf16(acc[0], afr, &bh[0]);
                mma_bf16(acc[1], afr, &bh[2]);
                mma_bf16(acc[0], afr, &bl[0]);
                mma_bf16(acc[1], afr, &bl[2]);
            }
        }
#undef ISSUEA
        __syncthreads();                   // all MMA done; A buffers reusable

        // ---- dump acc -> gs [64 s][36]
#pragma unroll
        for (int t8 = 0; t8 < 2; t8++) {
            int n  = warpN * 16 + t8 * 8 + (lane & 3) * 2;
            int s0 = warpM * 16 + (lane >> 2);
            gs[s0 * 36 + n]           = acc[t8][0];
            gs[s0 * 36 + n + 1]       = acc[t8][1];
            gs[(s0 + 8) * 36 + n]     = acc[t8][2];
            gs[(s0 + 8) * 36 + n + 1] = acc[t8][3];
        }
        __syncthreads();

        // ---- gate math: 512 cells, 2 per thread (Z from smem)
        __nv_bfloat16* ho = g_hbf + (size_t)((t + 1) & 1) * 2 * PLANE;
#pragma unroll
        for (int it = 0; it < 2; it++) {
            int cid = tid + 256 * it;           // = s*8 + j
            int s = cid >> 3, j = cid & 7;
            size_t row = (size_t)s * TT + t;
            float zi = zs[s * 40 +  0 + j] + gs[s * 36 +  0 + j];
            float zf = zs[s * 40 +  8 + j] + gs[s * 36 +  8 + j];
            float zo = zs[s * 40 + 16 + j] + gs[s * 36 + 16 + j];
            float zg = zs[s * 40 + 24 + j] + gs[s * 36 + 24 + j];
            float c  = cc[cid];
            float cn = fsig(zf) * c + fsig(zi) * ftanh(zg);
            float hn = fsig(zo) * ftanh(cn);
            cc[cid] = cn;
            int u = blk * 8 + j;
            outSeq[row * HID + u] = hn;
            ho[(size_t)s * 1024 + u] = __float2bfloat16(hn);
        }
        __syncthreads();                   // zs fully consumed before refill

        if (t < TT - 1) {
            // prefetch Z(t+1) — hides DRAM latency behind barrier + chunk 0
            int s = tid >> 2, gt = tid & 3;
            const float* src = Z + ((size_t)s * TT + t + 1) * G4 + gt * HID + blk * 8;
            uint32_t dst = saZ + s * 160 + gt * 32;
            cpasync16(dst,      src);
            cpasync16(dst + 16, src + 4);
            CP_COMMIT();
            flagbar(fSelf, blk, tid, t + 2);
        }
    }
}

// =============================================================================
extern "C" void kernel_launch(void* const* d_in, const int* in_sizes, int n_in,
                              void* d_out, int out_size)
{
    const float* x  = (const float*)d_in[0];
    const float* W0 = (const float*)d_in[1];
    const float* b0 = (const float*)d_in[2];
    const float* W1 = (const float*)d_in[3];
    const float* b1 = (const float*)d_in[4];
    float* out = (float*)d_out;

    float *pZ = nullptr, *pH0 = nullptr;
    __nv_bfloat16 *pA = nullptr, *pB = nullptr;
    cudaGetSymbolAddress((void**)&pZ,  g_Z);
    cudaGetSymbolAddress((void**)&pH0, g_H0);
    cudaGetSymbolAddress((void**)&pA,  g_Apack);
    cudaGetSymbolAddress((void**)&pB,  g_Bpack);

    cudaFuncSetAttribute(lstm_recur, cudaFuncAttributeMaxDynamicSharedMemorySize,
                         R_SMEM);

    dim3 gg(NT, MT);

    // ---- layer 0: Z = bf16x3-GEMM(x, W0_x) + b0   (K=512)
    pack3<<<1024, 256>>>(x,  DD,       6, MROWS, pA, 0);
    pack3<<<256,  256>>>(W0, DD + HID, 6, G4,    pB, 1);
    gemm_hmma<<<gg, 256>>>(pA, pB, b0, pZ, 3 * DD);
    lstm_recur<<<NBLK, 256, R_SMEM>>>(W0, DD + HID, DD, pZ, pH0, 0);

    // ---- layer 1   (K=1024)
    pack3<<<1024, 256>>>(pH0, HID,     7, MROWS, pA, 0);
    pack3<<<256,  256>>>(W1,  2 * HID, 7, G4,    pB, 1);
    gemm_hmma<<<gg, 256>>>(pA, pB, b1, pZ, 3 * HID);
    lstm_recur<<<NBLK, 256, R_SMEM>>>(W1, 2 * HID, HID, pZ, out, 1);
}

// round 11
// speedup vs baseline: 2.5786x; 1.0838x over previous
#include <cuda_runtime.h>
#include <cuda_bf16.h>
#include <cstdint>

#define BSZ   64
#define TT    512
#define DD    512
#define HID   1024
#define G4    4096
#define MROWS (BSZ*TT)             // 32768
#define NBLK  128
#define MT    (MROWS/128)          // 256 M tiles
#define NT    (G4/128)             // 32  N tiles
#define PLANE 65536                // 64 x 1024 bf16 elements per plane

// ---------------- device scratch -------------------------------------------
__device__ __align__(16) float    g_Z[(size_t)MROWS * G4];      // 512 MB
__device__ __align__(16) float    g_H0[(size_t)MROWS * HID];    // 128 MB
__device__ __align__(16) __nv_bfloat16 g_hbf[4 * PLANE];        // ping-pong h (hi)
__device__ int g_flags[2][NBLK];
__device__ __align__(16) __nv_bfloat16 g_Apack[(size_t)MROWS * 2 * HID]; // 128 MB (hi|lo)
__device__ __align__(16) __nv_bfloat16 g_Bpack[(size_t)G4 * 2 * HID];    // 16 MB (hi|lo)

// ---------------- PTX helpers (family-portable) ------------------------------
__device__ __forceinline__ uint32_t smem_u32(const void* p)
{
    uint32_t a;
    asm("{ .reg .u64 t; cvta.to.shared.u64 t, %1; cvt.u32.u64 %0, t; }"
        : "=r"(a) : "l"(p));
    return a;
}
__device__ __forceinline__ void cpasync16(uint32_t dst, const void* src)
{
    asm volatile("cp.async.cg.shared.global [%0], [%1], 16;"
                 :: "r"(dst), "l"(src));
}
#define CP_COMMIT() asm volatile("cp.async.commit_group;")
#define CP_WAIT1()  asm volatile("cp.async.wait_group 1;")
#define CP_WAIT0()  asm volatile("cp.async.wait_group 0;")

__device__ __forceinline__ void ldsm4(uint32_t* r, uint32_t addr)
{
    asm volatile("ldmatrix.sync.aligned.m8n8.x4.shared.b16 {%0,%1,%2,%3}, [%4];"
                 : "=r"(r[0]), "=r"(r[1]), "=r"(r[2]), "=r"(r[3]) : "r"(addr));
}
__device__ __forceinline__ void mma_bf16(float* c, const uint32_t* a,
                                         const uint32_t* b)
{
    asm volatile(
        "mma.sync.aligned.m16n8k16.row.col.f32.bf16.bf16.f32 "
        "{%0,%1,%2,%3}, {%4,%5,%6,%7}, {%8,%9}, {%0,%1,%2,%3};"
        : "+f"(c[0]), "+f"(c[1]), "+f"(c[2]), "+f"(c[3])
        : "r"(a[0]), "r"(a[1]), "r"(a[2]), "r"(a[3]), "r"(b[0]), "r"(b[1]));
}

// =============================================================================
// packHL: fp32 -> bf16 [hi | lo], row-major width 2K (used for both A and B)
// =============================================================================
__global__ void packHL(const float* __restrict__ src, int lds, int cslog2,
                       long nrows, __nv_bfloat16* __restrict__ dst)
{
    const int K = 8 << cslog2;
    const long total = nrows << cslog2;
    for (long g = (long)blockIdx.x * blockDim.x + threadIdx.x; g < total;
         g += (long)gridDim.x * blockDim.x) {
        long r  = g >> cslog2;
        int col = (int)(g & ((1 << cslog2) - 1)) << 3;
        const float* sp = src + r * lds + col;
        float4 v0 = *(const float4*)sp;
        float4 v1 = *(const float4*)(sp + 4);
        float vv[8] = {v0.x, v0.y, v0.z, v0.w, v1.x, v1.y, v1.z, v1.w};
        union { __nv_bfloat16 b[8]; uint4 u; } H, L;
#pragma unroll
        for (int j = 0; j < 8; j++) {
            __nv_bfloat16 h = __float2bfloat16(vv[j]);
            H.b[j] = h;
            L.b[j] = __float2bfloat16(vv[j] - __bfloat162float(h));
        }
        __nv_bfloat16* d = dst + r * (2 * K) + col;
        *(uint4*)d       = H.u;
        *(uint4*)(d + K) = L.u;
    }
}

// =============================================================================
// HMMA GEMM v3 (3-term): C = Ah*Bh + Al*Bh + Ah*Bl + bias
// 128x128 tile, BK=32; per chunk load {Ahi, Alo, Bhi, Blo} (32KB/stage, 3 stages)
// =============================================================================
__global__ __launch_bounds__(256)
void gemm_hmma3(const __nv_bfloat16* __restrict__ Ap,
                const __nv_bfloat16* __restrict__ Bp,
                const float* __restrict__ bias,
                float* __restrict__ C, int K)
{
    extern __shared__ char gsm[];
    const int tid  = threadIdx.x;
    const int wid  = tid >> 5, lane = tid & 31;
    const int warpM = wid & 3, warpN = wid >> 2;
    const int m0 = blockIdx.y * 128, n0 = blockIdx.x * 128;
    const int nk = K >> 5;
    const int K2 = 2 * K;
    const uint32_t sa = smem_u32(gsm);

    const int lrow0 = tid >> 2,         lc0 = tid & 3;
    const int lrow1 = (tid + 256) >> 2, lc1 = (tid + 256) & 3;

    float acc[2][8][4];
#pragma unroll
    for (int a = 0; a < 2; a++)
#pragma unroll
        for (int b = 0; b < 8; b++)
#pragma unroll
            for (int c = 0; c < 4; c++) acc[a][b][c] = 0.f;

#define ISSUE3(stage, kt)                                                        \
    do {                                                                         \
        uint32_t dAh = sa + (stage) * 32768;                                     \
        uint32_t dAl = dAh + 8192;                                               \
        uint32_t dBh = dAh + 16384;                                              \
        uint32_t dBl = dAh + 24576;                                              \
        uint32_t so0 = lrow0 * 64 + ((lc0 ^ (lrow0 & 3)) << 4);                  \
        uint32_t so1 = lrow1 * 64 + ((lc1 ^ (lrow1 & 3)) << 4);                  \
        cpasync16(dAh + so0, Ap + (size_t)(m0 + lrow0) * K2 + (kt) + lc0 * 8);   \
        cpasync16(dAh + so1, Ap + (size_t)(m0 + lrow1) * K2 + (kt) + lc1 * 8);   \
        cpasync16(dAl + so0, Ap + (size_t)(m0 + lrow0) * K2 + K + (kt) + lc0 * 8);\
        cpasync16(dAl + so1, Ap + (size_t)(m0 + lrow1) * K2 + K + (kt) + lc1 * 8);\
        cpasync16(dBh + so0, Bp + (size_t)(n0 + lrow0) * K2 + (kt) + lc0 * 8);   \
        cpasync16(dBh + so1, Bp + (size_t)(n0 + lrow1) * K2 + (kt) + lc1 * 8);   \
        cpasync16(dBl + so0, Bp + (size_t)(n0 + lrow0) * K2 + K + (kt) + lc0 * 8);\
        cpasync16(dBl + so1, Bp + (size_t)(n0 + lrow1) * K2 + K + (kt) + lc1 * 8);\
    } while (0)

    ISSUE3(0, 0);  CP_COMMIT();
    ISSUE3(1, 32); CP_COMMIT();

    const int g  = lane >> 3;
    const int lr = lane & 7;
    const int arow0 = warpM * 32 + (g & 1) * 8 + lr;
    const int brow0 = warpN * 64 + (g >> 1) * 8 + lr;

    for (int i = 0; i < nk; i++) {
        CP_WAIT1();
        __syncthreads();
        const uint32_t bAh = sa + (i % 3) * 32768;
        const uint32_t bAl = bAh + 8192;
        const uint32_t bBh = bAh + 16384;
        const uint32_t bBl = bAh + 24576;
#pragma unroll
        for (int kk = 0; kk < 2; kk++) {
            uint32_t afh[2][4], afl[2][4];
#pragma unroll
            for (int mh = 0; mh < 2; mh++) {
                int row = arow0 + mh * 16;
                int ch  = (2 * kk + (g >> 1)) ^ (row & 3);
                ldsm4(afh[mh], bAh + row * 64 + ch * 16);
                ldsm4(afl[mh], bAl + row * 64 + ch * 16);
            }
#pragma unroll
            for (int j = 0; j < 4; j++) {
                int row = brow0 + j * 16;
                int ch  = (2 * kk + (g & 1)) ^ (row & 3);
                uint32_t bh[4], bl[4];
                ldsm4(bh, bBh + row * 64 + ch * 16);
                ldsm4(bl, bBl + row * 64 + ch * 16);
#pragma unroll
                for (int mh = 0; mh < 2; mh++) {
                    mma_bf16(acc[mh][2 * j],     afh[mh], &bh[0]);
                    mma_bf16(acc[mh][2 * j + 1], afh[mh], &bh[2]);
                    mma_bf16(acc[mh][2 * j],     afl[mh], &bh[0]);
                    mma_bf16(acc[mh][2 * j + 1], afl[mh], &bh[2]);
                    mma_bf16(acc[mh][2 * j],     afh[mh], &bl[0]);
                    mma_bf16(acc[mh][2 * j + 1], afh[mh], &bl[2]);
                }
            }
        }
        __syncthreads();
        if (i + 2 < nk) ISSUE3((i + 2) % 3, (i + 2) * 32);
        CP_COMMIT();
    }
#undef ISSUE3

    // epilogue: acc + bias -> C
#pragma unroll
    for (int mh = 0; mh < 2; mh++)
#pragma unroll
        for (int j = 0; j < 8; j++) {
            int row = m0 + warpM * 32 + mh * 16 + (lane >> 2);
            int col = n0 + warpN * 64 + j * 8 + (lane & 3) * 2;
            float b0 = bias[col], b1 = bias[col + 1];
            float2 v0 = {acc[mh][j][0] + b0, acc[mh][j][1] + b1};
            float2 v1 = {acc[mh][j][2] + b0, acc[mh][j][3] + b1};
            *(float2*)(C + (size_t)row * G4 + col)       = v0;
            *(float2*)(C + (size_t)(row + 8) * G4 + col) = v1;
        }
}

// =============================================================================
// Persistent HMMA recurrence (unchanged from R8 — at its HMMA floor, passing)
// =============================================================================
__device__ __forceinline__ float fsig(float x)  { return __fdividef(1.f, 1.f + __expf(-x)); }
__device__ __forceinline__ float ftanh(float x) { return 2.f * __fdividef(1.f, 1.f + __expf(-2.f * x)) - 1.f; }

#define R_WHI 0                         // 65536
#define R_WLO 65536                     // 65536
#define R_AB  131072                    // 2 x 32768 double-buffered A chunks
#define R_ZS  196608                    // 64*40*4 = 10240 staged Z
#define R_GS  206848                    // 64*36*4 = 9216
#define R_CC  216064                    // 512*4
#define R_SMEM 218112

__device__ __forceinline__ void flagbar(volatile int* f, int blk, int tid, int target)
{
    __threadfence();
    __syncthreads();
    if (tid == 0) f[blk] = target;
    if (tid < NBLK) { while (f[tid] < target) { } }
    __syncthreads();
}

__global__ __launch_bounds__(256, 1)
void lstm_recur(const float* __restrict__ W, int ldw, int hoff,
                const float* __restrict__ Z,
                float* __restrict__ outSeq, int sel)
{
    extern __shared__ char sm[];
    float* zs = (float*)(sm + R_ZS);
    float* gs = (float*)(sm + R_GS);
    float* cc = (float*)(sm + R_CC);

    const int tid = threadIdx.x, blk = blockIdx.x;
    const int lane = tid & 31, wid = tid >> 5;
    const int warpM = wid & 3, warpN = wid >> 2;
    const int g = lane >> 3, lr = lane & 7;

    volatile int* fSelf  = (volatile int*)g_flags[sel];
    volatile int* fOther = (volatile int*)g_flags[sel ^ 1];
    if (tid == 0) fOther[blk] = 0;

    const uint32_t saW = smem_u32(sm);
    const uint32_t saA = saW + R_AB;
    const uint32_t saZ = saW + R_ZS;

    // ---- prologue: recurrent weights -> swizzled bf16 hi/lo in smem
    for (int idx = tid; idx < 32 * 1024; idx += 256) {
        int r = idx >> 10, k = idx & 1023;
        float v = W[(size_t)((r >> 3) * HID + blk * 8 + (r & 7)) * ldw + hoff + k];
        __nv_bfloat16 h = __float2bfloat16(v);
        __nv_bfloat16 l = __float2bfloat16(v - __bfloat162float(h));
        uint32_t off = r * 2048 + ((((k >> 3) ^ (r & 7)) << 4)) + (k & 7) * 2;
        *(__nv_bfloat16*)(sm + R_WHI + off) = h;
        *(__nv_bfloat16*)(sm + R_WLO + off) = l;
    }
    for (int i = tid; i < 512; i += 256) cc[i] = 0.f;
    for (int i = tid; i < 512; i += 256) {
        int s = i >> 3, j = i & 7;
        g_hbf[(size_t)s * 1024 + blk * 8 + j] = __float2bfloat16(0.f);
    }
    {
        int s = tid >> 2, gt = tid & 3;
        const float* src = Z + ((size_t)s * TT + 0) * G4 + gt * HID + blk * 8;
        uint32_t dst = saZ + s * 160 + gt * 32;
        cpasync16(dst,      src);
        cpasync16(dst + 16, src + 4);
    }
    CP_COMMIT();
    flagbar(fSelf, blk, tid, 1);

    const int arow = warpM * 16 + (g & 1) * 8 + lr;
    const int brow = warpN * 16 + (g >> 1) * 8 + lr;
    const uint32_t aBase = saA + arow * 512;
    const int aXor = arow & 7, bXor = brow & 7;
    const int aC0 = g >> 1, bC0 = g & 1;
    const uint32_t bHi = saW + R_WHI + brow * 2048;
    const uint32_t bLo = saW + R_WLO + brow * 2048;

    for (int t = 0; t < TT; t++) {
        const __nv_bfloat16* hin = g_hbf + (size_t)(t & 1) * 2 * PLANE;

        float acc[2][4];
#pragma unroll
        for (int a = 0; a < 2; a++)
#pragma unroll
            for (int c = 0; c < 4; c++) acc[a][c] = 0.f;

#define ISSUEA(j)                                                                \
    do {                                                                         \
        const __nv_bfloat16* src = hin + (j) * 256;                              \
        uint32_t dst = saA + ((j) & 1) * 32768;                                  \
        _Pragma("unroll")                                                        \
        for (int q = 0; q < 8; q++) {                                            \
            int f = tid + 256 * q;                                               \
            int s = f >> 5, c = f & 31;                                          \
            cpasync16(dst + s * 512 + ((c ^ (s & 7)) << 4),                      \
                      src + (size_t)s * 1024 + c * 8);                           \
        }                                                                        \
        CP_COMMIT();                                                             \
    } while (0)

        ISSUEA(0);
#pragma unroll
        for (int i = 0; i < 4; i++) {
            CP_WAIT0();
            __syncthreads();
            if (i < 3) ISSUEA(i + 1);
            const uint32_t ab = aBase + (i & 1) * 32768;
#pragma unroll
            for (int kk = 0; kk < 16; kk++) {
                const int k16g = i * 16 + kk;
                uint32_t afr[4], bh[4], bl[4];
                ldsm4(afr, ab + (((2 * kk + aC0) ^ aXor) << 4));
                const uint32_t bcix = ((2 * k16g + bC0) ^ bXor) << 4;
                ldsm4(bh, bHi + bcix);
                ldsm4(bl, bLo + bcix);
                mma_bf16(acc[0], afr, &bh[0]);
                mma_bf16(acc[1], afr, &bh[2]);
                mma_bf16(acc[0], afr, &bl[0]);
                mma_bf16(acc[1], afr, &bl[2]);
            }
        }
#undef ISSUEA
        __syncthreads();

#pragma unroll
        for (int t8 = 0; t8 < 2; t8++) {
            int n  = warpN * 16 + t8 * 8 + (lane & 3) * 2;
            int s0 = warpM * 16 + (lane >> 2);
            gs[s0 * 36 + n]           = acc[t8][0];
            gs[s0 * 36 + n + 1]       = acc[t8][1];
            gs[(s0 + 8) * 36 + n]     = acc[t8][2];
            gs[(s0 + 8) * 36 + n + 1] = acc[t8][3];
        }
        __syncthreads();

        __nv_bfloat16* ho = g_hbf + (size_t)((t + 1) & 1) * 2 * PLANE;
#pragma unroll
        for (int it = 0; it < 2; it++) {
            int cid = tid + 256 * it;
            int s = cid >> 3, j = cid & 7;
            size_t row = (size_t)s * TT + t;
            float zi = zs[s * 40 +  0 + j] + gs[s * 36 +  0 + j];
            float zf = zs[s * 40 +  8 + j] + gs[s * 36 +  8 + j];
            float zo = zs[s * 40 + 16 + j] + gs[s * 36 + 16 + j];
            float zg = zs[s * 40 + 24 + j] + gs[s * 36 + 24 + j];
            float c  = cc[cid];
            float cn = fsig(zf) * c + fsig(zi) * ftanh(zg);
            float hn = fsig(zo) * ftanh(cn);
            cc[cid] = cn;
            int u = blk * 8 + j;
            outSeq[row * HID + u] = hn;
            ho[(size_t)s * 1024 + u] = __float2bfloat16(hn);
        }
        __syncthreads();

        if (t < TT - 1) {
            int s = tid >> 2, gt = tid & 3;
            const float* src = Z + ((size_t)s * TT + t + 1) * G4 + gt * HID + blk * 8;
            uint32_t dst = saZ + s * 160 + gt * 32;
            cpasync16(dst,      src);
            cpasync16(dst + 16, src + 4);
            CP_COMMIT();
            flagbar(fSelf, blk, tid, t + 2);
        }
    }
}

// =============================================================================
extern "C" void kernel_launch(void* const* d_in, const int* in_sizes, int n_in,
                              void* d_out, int out_size)
{
    const float* x  = (const float*)d_in[0];
    const float* W0 = (const float*)d_in[1];
    const float* b0 = (const float*)d_in[2];
    const float* W1 = (const float*)d_in[3];
    const float* b1 = (const float*)d_in[4];
    float* out = (float*)d_out;

    float *pZ = nullptr, *pH0 = nullptr;
    __nv_bfloat16 *pA = nullptr, *pB = nullptr;
    cudaGetSymbolAddress((void**)&pZ,  g_Z);
    cudaGetSymbolAddress((void**)&pH0, g_H0);
    cudaGetSymbolAddress((void**)&pA,  g_Apack);
    cudaGetSymbolAddress((void**)&pB,  g_Bpack);

    const int gemm_smem = 3 * 32768;   // 96 KB
    cudaFuncSetAttribute(gemm_hmma3, cudaFuncAttributeMaxDynamicSharedMemorySize,
                         gemm_smem);
    cudaFuncSetAttribute(lstm_recur, cudaFuncAttributeMaxDynamicSharedMemorySize,
                         R_SMEM);

    dim3 gg(NT, MT);

    // ---- layer 0: Z = Ah*Bh + Al*Bh + Ah*Bl + b0   (K=512, cslog2=6)
    packHL<<<2048, 256>>>(x,  DD,       6, MROWS, pA);
    packHL<<<256,  256>>>(W0, DD + HID, 6, G4,    pB);
    gemm_hmma3<<<gg, 256, gemm_smem>>>(pA, pB, b0, pZ, DD);
    lstm_recur<<<NBLK, 256, R_SMEM>>>(W0, DD + HID, DD, pZ, pH0, 0);

    // ---- layer 1   (K=1024, cslog2=7)
    packHL<<<2048, 256>>>(pH0, HID,     7, MROWS, pA);
    packHL<<<512,  256>>>(W1,  2 * HID, 7, G4,    pB);
    gemm_hmma3<<<gg, 256, gemm_smem>>>(pA, pB, b1, pZ, HID);
    lstm_recur<<<NBLK, 256, R_SMEM>>>(W1, 2 * HID, HID, pZ, out, 1);
}

// round 17
// speedup vs baseline: 2.7429x; 1.0637x over previous
#include <cuda_runtime.h>
#include <cuda_bf16.h>
#include <cstdint>

#define BSZ   64
#define TT    512
#define DD    512
#define HID   1024
#define G4    4096
#define MROWS (BSZ*TT)             // 32768
#define NBLK  128
#define MT    (MROWS/128)          // 256 M tiles
#define NT    (G4/128)             // 32  N tiles
#define PLANE 65536                // 64 x 1024 bf16 elements per plane

// ---------------- device scratch -------------------------------------------
__device__ __align__(16) float    g_Z[(size_t)MROWS * G4];      // 512 MB
__device__ __align__(16) __nv_bfloat16 g_hbf[4 * PLANE];        // ping-pong h (hi)
__device__ int g_flags[2][NBLK];
__device__ __align__(16) __nv_bfloat16 g_Apack[(size_t)MROWS * 2 * HID]; // 128 MB (hi|lo)
__device__ __align__(16) __nv_bfloat16 g_Bpack[(size_t)G4 * 2 * HID];    // 16 MB (hi|lo)

// ---------------- PTX helpers (family-portable) ------------------------------
__device__ __forceinline__ uint32_t smem_u32(const void* p)
{
    uint32_t a;
    asm("{ .reg .u64 t; cvta.to.shared.u64 t, %1; cvt.u32.u64 %0, t; }"
        : "=r"(a) : "l"(p));
    return a;
}
__device__ __forceinline__ void cpasync16(uint32_t dst, const void* src)
{
    asm volatile("cp.async.cg.shared.global [%0], [%1], 16;"
                 :: "r"(dst), "l"(src));
}
#define CP_COMMIT() asm volatile("cp.async.commit_group;")
#define CP_WAIT1()  asm volatile("cp.async.wait_group 1;")
#define CP_WAIT0()  asm volatile("cp.async.wait_group 0;")

__device__ __forceinline__ void ldsm4(uint32_t* r, uint32_t addr)
{
    asm volatile("ldmatrix.sync.aligned.m8n8.x4.shared.b16 {%0,%1,%2,%3}, [%4];"
                 : "=r"(r[0]), "=r"(r[1]), "=r"(r[2]), "=r"(r[3]) : "r"(addr));
}
__device__ __forceinline__ void mma_bf16(float* c, const uint32_t* a,
                                         const uint32_t* b)
{
    asm volatile(
        "mma.sync.aligned.m16n8k16.row.col.f32.bf16.bf16.f32 "
        "{%0,%1,%2,%3}, {%4,%5,%6,%7}, {%8,%9}, {%0,%1,%2,%3};"
        : "+f"(c[0]), "+f"(c[1]), "+f"(c[2]), "+f"(c[3])
        : "r"(a[0]), "r"(a[1]), "r"(a[2]), "r"(a[3]), "r"(b[0]), "r"(b[1]));
}

// =============================================================================
// packHL: fp32 -> bf16 [hi | lo], row-major width 2K
// =============================================================================
__global__ void packHL(const float* __restrict__ src, int lds, int cslog2,
                       long nrows, __nv_bfloat16* __restrict__ dst)
{
    const int K = 8 << cslog2;
    const long total = nrows << cslog2;
    for (long g = (long)blockIdx.x * blockDim.x + threadIdx.x; g < total;
         g += (long)gridDim.x * blockDim.x) {
        long r  = g >> cslog2;
        int col = (int)(g & ((1 << cslog2) - 1)) << 3;
        const float* sp = src + r * lds + col;
        float4 v0 = *(const float4*)sp;
        float4 v1 = *(const float4*)(sp + 4);
        float vv[8] = {v0.x, v0.y, v0.z, v0.w, v1.x, v1.y, v1.z, v1.w};
        union { __nv_bfloat16 b[8]; uint4 u; } H, L;
#pragma unroll
        for (int j = 0; j < 8; j++) {
            __nv_bfloat16 h = __float2bfloat16(vv[j]);
            H.b[j] = h;
            L.b[j] = __float2bfloat16(vv[j] - __bfloat162float(h));
        }
        __nv_bfloat16* d = dst + r * (2 * K) + col;
        *(uint4*)d       = H.u;
        *(uint4*)(d + K) = L.u;
    }
}

// =============================================================================
// HMMA GEMM v4 (3-term, 64x64 warp tiles): C = Ah*Bh + Al*Bh + Ah*Bl + bias
// CTA 128x128, 4 warps (2x2), BK=32, 3 stages x 32KB, 2 CTAs/SM.
// =============================================================================
__global__ __launch_bounds__(128)
void gemm_hmma4(const __nv_bfloat16* __restrict__ Ap,
                const __nv_bfloat16* __restrict__ Bp,
                const float* __restrict__ bias,
                float* __restrict__ C, int K)
{
    extern __shared__ char gsm[];
    const int tid  = threadIdx.x;
    const int wid  = tid >> 5, lane = tid & 31;
    const int warpM = wid & 1, warpN = wid >> 1;
    const int m0 = blockIdx.y * 128, n0 = blockIdx.x * 128;
    const int nk = K >> 5;
    const int K2 = 2 * K;
    const uint32_t sa = smem_u32(gsm);

    float acc[4][8][4];
#pragma unroll
    for (int a = 0; a < 4; a++)
#pragma unroll
        for (int b = 0; b < 8; b++)
#pragma unroll
            for (int c = 0; c < 4; c++) acc[a][b][c] = 0.f;

#define ISSUE4(stage, kt)                                                        \
    do {                                                                         \
        uint32_t dAh = sa + (stage) * 32768;                                     \
        uint32_t dAl = dAh + 8192;                                               \
        uint32_t dBh = dAh + 16384;                                              \
        uint32_t dBl = dAh + 24576;                                              \
        _Pragma("unroll")                                                        \
        for (int q = 0; q < 4; q++) {                                            \
            int f = tid + 128 * q;                                               \
            int row = f >> 2, c = f & 3;                                         \
            uint32_t so = row * 64 + ((c ^ (row & 3)) << 4);                     \
            cpasync16(dAh + so, Ap + (size_t)(m0 + row) * K2 + (kt) + c * 8);    \
            cpasync16(dAl + so, Ap + (size_t)(m0 + row) * K2 + K + (kt) + c * 8);\
            cpasync16(dBh + so, Bp + (size_t)(n0 + row) * K2 + (kt) + c * 8);    \
            cpasync16(dBl + so, Bp + (size_t)(n0 + row) * K2 + K + (kt) + c * 8);\
        }                                                                        \
    } while (0)

    ISSUE4(0, 0);  CP_COMMIT();
    ISSUE4(1, 32); CP_COMMIT();

    const int g  = lane >> 3;
    const int lr = lane & 7;
    const int arow0 = warpM * 64 + (g & 1) * 8 + lr;
    const int brow0 = warpN * 64 + (g >> 1) * 8 + lr;

    for (int i = 0; i < nk; i++) {
        CP_WAIT1();
        __syncthreads();
        const uint32_t bAh = sa + (i % 3) * 32768;
        const uint32_t bAl = bAh + 8192;
        const uint32_t bBh = bAh + 16384;
        const uint32_t bBl = bAh + 24576;
#pragma unroll
        for (int kk = 0; kk < 2; kk++) {
            uint32_t afh[4][4], afl[4][4];
#pragma unroll
            for (int mh = 0; mh < 4; mh++) {
                int row = arow0 + mh * 16;
                int ch  = (2 * kk + (g >> 1)) ^ (row & 3);
                ldsm4(afh[mh], bAh + row * 64 + ch * 16);
                ldsm4(afl[mh], bAl + row * 64 + ch * 16);
            }
#pragma unroll
            for (int j = 0; j < 4; j++) {
                int row = brow0 + j * 16;
                int ch  = (2 * kk + (g & 1)) ^ (row & 3);
                uint32_t bh[4], bl[4];
                ldsm4(bh, bBh + row * 64 + ch * 16);
                ldsm4(bl, bBl + row * 64 + ch * 16);
#pragma unroll
                for (int mh = 0; mh < 4; mh++) {
                    mma_bf16(acc[mh][2 * j],     afh[mh], &bh[0]);
                    mma_bf16(acc[mh][2 * j + 1], afh[mh], &bh[2]);
                    mma_bf16(acc[mh][2 * j],     afl[mh], &bh[0]);
                    mma_bf16(acc[mh][2 * j + 1], afl[mh], &bh[2]);
                    mma_bf16(acc[mh][2 * j],     afh[mh], &bl[0]);
                    mma_bf16(acc[mh][2 * j + 1], afh[mh], &bl[2]);
                }
            }
        }
        __syncthreads();
        if (i + 2 < nk) ISSUE4((i + 2) % 3, (i + 2) * 32);
        CP_COMMIT();
    }
#undef ISSUE4

    // epilogue: acc + bias -> C
#pragma unroll
    for (int mh = 0; mh < 4; mh++)
#pragma unroll
        for (int j = 0; j < 8; j++) {
            int row = m0 + warpM * 64 + mh * 16 + (lane >> 2);
            int col = n0 + warpN * 64 + j * 8 + (lane & 3) * 2;
            float b0 = bias[col], b1 = bias[col + 1];
            float2 v0 = {acc[mh][j][0] + b0, acc[mh][j][1] + b1};
            float2 v1 = {acc[mh][j][2] + b0, acc[mh][j][3] + b1};
            *(float2*)(C + (size_t)row * G4 + col)       = v0;
            *(float2*)(C + (size_t)(row + 8) * G4 + col) = v1;
        }
}

// =============================================================================
// Persistent HMMA recurrence (R8/R11 structure; output target is now
// layer-dependent: layer0 writes bf16 hi|lo packed A panel, layer1 writes fp32)
// =============================================================================
__device__ __forceinline__ float fsig(float x)  { return __fdividef(1.f, 1.f + __expf(-x)); }
__device__ __forceinline__ float ftanh(float x) { return 2.f * __fdividef(1.f, 1.f + __expf(-2.f * x)) - 1.f; }

#define R_WHI 0                         // 65536
#define R_WLO 65536                     // 65536
#define R_AB  131072                    // 2 x 32768 double-buffered A chunks
#define R_ZS  196608                    // 64*40*4 = 10240 staged Z
#define R_GS  206848                    // 64*36*4 = 9216
#define R_CC  216064                    // 512*4
#define R_SMEM 218112

__device__ __forceinline__ void flagbar(volatile int* f, int blk, int tid, int target)
{
    __threadfence();
    __syncthreads();
    if (tid == 0) f[blk] = target;
    if (tid < NBLK) { while (f[tid] < target) { } }
    __syncthreads();
}

__global__ __launch_bounds__(256, 1)
void lstm_recur(const float* __restrict__ W, int ldw, int hoff,
                const float* __restrict__ Z,
                float* __restrict__ outF,          // fp32 out (layer 1)
                __nv_bfloat16* __restrict__ outB,  // bf16 hi|lo packed out (layer 0)
                int sel)
{
    extern __shared__ char sm[];
    float* zs = (float*)(sm + R_ZS);
    float* gs = (float*)(sm + R_GS);
    float* cc = (float*)(sm + R_CC);

    const int tid = threadIdx.x, blk = blockIdx.x;
    const int lane = tid & 31, wid = tid >> 5;
    const int warpM = wid & 3, warpN = wid >> 2;
    const int g = lane >> 3, lr = lane & 7;

    volatile int* fSelf  = (volatile int*)g_flags[sel];
    volatile int* fOther = (volatile int*)g_flags[sel ^ 1];
    if (tid == 0) fOther[blk] = 0;

    const uint32_t saW = smem_u32(sm);
    const uint32_t saA = saW + R_AB;
    const uint32_t saZ = saW + R_ZS;

    // ---- prologue: recurrent weights -> swizzled bf16 hi/lo in smem
    for (int idx = tid; idx < 32 * 1024; idx += 256) {
        int r = idx >> 10, k = idx & 1023;
        float v = W[(size_t)((r >> 3) * HID + blk * 8 + (r & 7)) * ldw + hoff + k];
        __nv_bfloat16 h = __float2bfloat16(v);
        __nv_bfloat16 l = __float2bfloat16(v - __bfloat162float(h));
        uint32_t off = r * 2048 + ((((k >> 3) ^ (r & 7)) << 4)) + (k & 7) * 2;
        *(__nv_bfloat16*)(sm + R_WHI + off) = h;
        *(__nv_bfloat16*)(sm + R_WLO + off) = l;
    }
    for (int i = tid; i < 512; i += 256) cc[i] = 0.f;
    for (int i = tid; i < 512; i += 256) {
        int s = i >> 3, j = i & 7;
        g_hbf[(size_t)s * 1024 + blk * 8 + j] = __float2bfloat16(0.f);
    }
    {
        int s = tid >> 2, gt = tid & 3;
        const float* src = Z + ((size_t)s * TT + 0) * G4 + gt * HID + blk * 8;
        uint32_t dst = saZ + s * 160 + gt * 32;
        cpasync16(dst,      src);
        cpasync16(dst + 16, src + 4);
    }
    CP_COMMIT();
    flagbar(fSelf, blk, tid, 1);

    const int arow = warpM * 16 + (g & 1) * 8 + lr;
    const int brow = warpN * 16 + (g >> 1) * 8 + lr;
    const uint32_t aBase = saA + arow * 512;
    const int aXor = arow & 7, bXor = brow & 7;
    const int aC0 = g >> 1, bC0 = g & 1;
    const uint32_t bHi = saW + R_WHI + brow * 2048;
    const uint32_t bLo = saW + R_WLO + brow * 2048;

    for (int t = 0; t < TT; t++) {
        const __nv_bfloat16* hin = g_hbf + (size_t)(t & 1) * 2 * PLANE;

        float acc[2][4];
#pragma unroll
        for (int a = 0; a < 2; a++)
#pragma unroll
            for (int c = 0; c < 4; c++) acc[a][c] = 0.f;

#define ISSUEA(j)                                                                \
    do {                                                                         \
        const __nv_bfloat16* src = hin + (j) * 256;                              \
        uint32_t dst = saA + ((j) & 1) * 32768;                                  \
        _Pragma("unroll")                                                        \
        for (int q = 0; q < 8; q++) {                                            \
            int f = tid + 256 * q;                                               \
            int s = f >> 5, c = f & 31;                                          \
            cpasync16(dst + s * 512 + ((c ^ (s & 7)) << 4),                      \
                      src + (size_t)s * 1024 + c * 8);                           \
        }                                                                        \
        CP_COMMIT();                                                             \
    } while (0)

        ISSUEA(0);
#pragma unroll
        for (int i = 0; i < 4; i++) {
            CP_WAIT0();
            __syncthreads();
            if (i < 3) ISSUEA(i + 1);
            const uint32_t ab = aBase + (i & 1) * 32768;
#pragma unroll
            for (int kk = 0; kk < 16; kk++) {
                const int k16g = i * 16 + kk;
                uint32_t afr[4], bh[4], bl[4];
                ldsm4(afr, ab + (((2 * kk + aC0) ^ aXor) << 4));
                const uint32_t bcix = ((2 * k16g + bC0) ^ bXor) << 4;
                ldsm4(bh, bHi + bcix);
                ldsm4(bl, bLo + bcix);
                mma_bf16(acc[0], afr, &bh[0]);
                mma_bf16(acc[1], afr, &bh[2]);
                mma_bf16(acc[0], afr, &bl[0]);
                mma_bf16(acc[1], afr, &bl[2]);
            }
        }
#undef ISSUEA
        __syncthreads();

#pragma unroll
        for (int t8 = 0; t8 < 2; t8++) {
            int n  = warpN * 16 + t8 * 8 + (lane & 3) * 2;
            int s0 = warpM * 16 + (lane >> 2);
            gs[s0 * 36 + n]           = acc[t8][0];
            gs[s0 * 36 + n + 1]       = acc[t8][1];
            gs[(s0 + 8) * 36 + n]     = acc[t8][2];
            gs[(s0 + 8) * 36 + n + 1] = acc[t8][3];
        }
        __syncthreads();

        __nv_bfloat16* ho = g_hbf + (size_t)((t + 1) & 1) * 2 * PLANE;
#pragma unroll
        for (int it = 0; it < 2; it++) {
            int cid = tid + 256 * it;
            int s = cid >> 3, j = cid & 7;
            size_t row = (size_t)s * TT + t;
            float zi = zs[s * 40 +  0 + j] + gs[s * 36 +  0 + j];
            float zf = zs[s * 40 +  8 + j] + gs[s * 36 +  8 + j];
            float zo = zs[s * 40 + 16 + j] + gs[s * 36 + 16 + j];
            float zg = zs[s * 40 + 24 + j] + gs[s * 36 + 24 + j];
            float c  = cc[cid];
            float cn = fsig(zf) * c + fsig(zi) * ftanh(zg);
            float hn = fsig(zo) * ftanh(cn);
            cc[cid] = cn;
            int u = blk * 8 + j;
            __nv_bfloat16 hh = __float2bfloat16(hn);
            if (outB) {
                __nv_bfloat16 hl = __float2bfloat16(hn - __bfloat162float(hh));
                outB[row * 2048 + u]        = hh;   // A_hi for layer-1 GEMM
                outB[row * 2048 + 1024 + u] = hl;   // A_lo
            } else {
                outF[row * HID + u] = hn;           // final fp32 output
            }
            ho[(size_t)s * 1024 + u] = hh;
        }
        __syncthreads();

        if (t < TT - 1) {
            int s = tid >> 2, gt = tid & 3;
            const float* src = Z + ((size_t)s * TT + t + 1) * G4 + gt * HID + blk * 8;
            uint32_t dst = saZ + s * 160 + gt * 32;
            cpasync16(dst,      src);
            cpasync16(dst + 16, src + 4);
            CP_COMMIT();
            flagbar(fSelf, blk, tid, t + 2);
        }
    }
}

// =============================================================================
extern "C" void kernel_launch(void* const* d_in, const int* in_sizes, int n_in,
                              void* d_out, int out_size)
{
    const float* x  = (const float*)d_in[0];
    const float* W0 = (const float*)d_in[1];
    const float* b0 = (const float*)d_in[2];
    const float* W1 = (const float*)d_in[3];
    const float* b1 = (const float*)d_in[4];
    float* out = (float*)d_out;

    float* pZ = nullptr;
    __nv_bfloat16 *pA = nullptr, *pB = nullptr;
    cudaGetSymbolAddress((void**)&pZ, g_Z);
    cudaGetSymbolAddress((void**)&pA, g_Apack);
    cudaGetSymbolAddress((void**)&pB, g_Bpack);

    const int gemm_smem = 3 * 32768;   // 96 KB
    cudaFuncSetAttribute(gemm_hmma4, cudaFuncAttributeMaxDynamicSharedMemorySize,
                         gemm_smem);
    cudaFuncSetAttribute(lstm_recur, cudaFuncAttributeMaxDynamicSharedMemorySize,
                         R_SMEM);

    dim3 gg(NT, MT);

    // ---- layer 0: Z = Ah*Bh + Al*Bh + Ah*Bl + b0   (K=512, cslog2=6)
    packHL<<<2048, 256>>>(x,  DD,       6, MROWS, pA);
    packHL<<<256,  256>>>(W0, DD + HID, 6, G4,    pB);
    gemm_hmma4<<<gg, 128, gemm_smem>>>(pA, pB, b0, pZ, DD);
    // layer-0 recurrence writes the layer-1 A panel (bf16 hi|lo) directly
    lstm_recur<<<NBLK, 256, R_SMEM>>>(W0, DD + HID, DD, pZ, nullptr, pA, 0);

    // ---- layer 1   (K=1024, cslog2=7) — no packA needed
    packHL<<<512,  256>>>(W1,  2 * HID, 7, G4,    pB);
    gemm_hmma4<<<gg, 128, gemm_smem>>>(pA, pB, b1, pZ, HID);
    lstm_recur<<<NBLK, 256, R_SMEM>>>(W1, 2 * HID, HID, pZ, out, nullptr, 1);
}